// round 1
// baseline (speedup 1.0000x reference)
#include <cuda_runtime.h>
#include <cuda_bf16.h>
#include <cstdint>

// Problem constants
#define BB 2
#define LL 2048
#define DD 1024
#define HH 16
#define HD 64
#define MM (BB*LL)          // 4096 rows
#define E3 (3*DD)           // 3072
#define PH (DD/2)           // 512 phase dims

// Scratch (device globals; no runtime allocation allowed)
__device__ float g_qkv[MM * E3];          // 50 MB  (B*L, 3*D) rotated in place
__device__ float g_phases[MM * PH];       // 8 MB
__device__ float g_o[MM * DD];            // 16 MB  attention output (b,l,h,hd)
__device__ float g_projT[PH * DD];        // 2 MB   proj transposed to (j, d)

// ---------------------------------------------------------------------------
// Generic NT GEMM: C[M,N] = A[M,K] @ B[N,K]^T (+ bias[N])
// 64x64 tile, BK=16, 256 threads, 4x4 per thread.
// Requires M%64==0, N%64==0, K%16==0 (true for all three calls).
// ---------------------------------------------------------------------------
__global__ __launch_bounds__(256) void gemm_nt_64x64(
    const float* __restrict__ A, const float* __restrict__ Bm,
    const float* __restrict__ bias, float* __restrict__ C,
    int M, int N, int K)
{
    __shared__ float As[16][68];   // As[k][m]
    __shared__ float Bs[16][68];   // Bs[k][n]
    const int tid = threadIdx.x;
    const int bm = blockIdx.y * 64;
    const int bn = blockIdx.x * 64;
    const int tx = tid & 15;
    const int ty = tid >> 4;
    const int lr = tid >> 2;          // 0..63 tile row
    const int lc = (tid & 3) << 2;    // 0,4,8,12 within BK

    const float* Aptr = A + (size_t)(bm + lr) * K + lc;
    const float* Bptr = Bm + (size_t)(bn + lr) * K + lc;

    float acc[4][4] = {};

    for (int k0 = 0; k0 < K; k0 += 16) {
        float4 av = *(const float4*)(Aptr + k0);
        float4 bv = *(const float4*)(Bptr + k0);
        __syncthreads();
        As[lc + 0][lr] = av.x; As[lc + 1][lr] = av.y;
        As[lc + 2][lr] = av.z; As[lc + 3][lr] = av.w;
        Bs[lc + 0][lr] = bv.x; Bs[lc + 1][lr] = bv.y;
        Bs[lc + 2][lr] = bv.z; Bs[lc + 3][lr] = bv.w;
        __syncthreads();
        #pragma unroll
        for (int kk = 0; kk < 16; kk++) {
            float ar[4], br[4];
            *(float4*)ar = *(const float4*)&As[kk][ty * 4];
            *(float4*)br = *(const float4*)&Bs[kk][tx * 4];
            #pragma unroll
            for (int i = 0; i < 4; i++)
                #pragma unroll
                for (int j = 0; j < 4; j++)
                    acc[i][j] = fmaf(ar[i], br[j], acc[i][j]);
        }
    }

    #pragma unroll
    for (int i = 0; i < 4; i++) {
        const size_t row = bm + ty * 4 + i;
        #pragma unroll
        for (int j = 0; j < 4; j++) {
            const int col = bn + tx * 4 + j;
            float v = acc[i][j];
            if (bias) v += bias[col];
            C[row * N + col] = v;
        }
    }
}

// ---------------------------------------------------------------------------
// proj (D, PH) row-major -> projT (PH, D) so the phase GEMM is NT form.
// ---------------------------------------------------------------------------
__global__ void transpose_proj(const float* __restrict__ P, float* __restrict__ PT)
{
    int idx = blockIdx.x * blockDim.x + threadIdx.x;   // D*PH threads
    int d = idx >> 9;        // /512
    int j = idx & 511;
    PT[(size_t)j * DD + d] = P[idx];
}

// ---------------------------------------------------------------------------
// In-place rotation of q and k inside the qkv buffer using phases.
// One thread per (m, h, j) with j in [0,32).
// ---------------------------------------------------------------------------
__global__ void rope_rot(float* __restrict__ qkv, const float* __restrict__ phases)
{
    int idx = blockIdx.x * blockDim.x + threadIdx.x;   // MM*PH = 2M threads
    int m = idx >> 9;
    int r = idx & 511;
    int h = r >> 5;
    int j = r & 31;
    float ph = phases[idx];
    float s, c;
    __sincosf(ph, &s, &c);
    size_t base = (size_t)m * E3 + h * HD + j;
    float q1 = qkv[base], q2 = qkv[base + 32];
    qkv[base]        = q1 * c - q2 * s;
    qkv[base + 32]   = q1 * s + q2 * c;
    float k1 = qkv[base + DD], k2 = qkv[base + DD + 32];
    qkv[base + DD]      = k1 * c - k2 * s;
    qkv[base + DD + 32] = k1 * s + k2 * c;
}

// ---------------------------------------------------------------------------
// Flash attention. grid = (L/64, H, B), 256 threads.
// Br=Bc=64, HD=64. Online softmax, per-thread 4x4 register tiles.
// Smem: Qs[d][r], Ks[d][c] (transposed for conflict-free S loop),
//       Vs[kc][d], Ps[r][kc].
// ---------------------------------------------------------------------------
#define FLASH_SMEM (4 * 64 * 68 * 4)

__global__ __launch_bounds__(256) void flash_attn(
    const float* __restrict__ qkv, float* __restrict__ O)
{
    extern __shared__ float sm[];
    float (*Qs)[68] = (float(*)[68])(sm);
    float (*Ks)[68] = (float(*)[68])(sm + 64 * 68);
    float (*Vs)[68] = (float(*)[68])(sm + 2 * 64 * 68);
    float (*Ps)[68] = (float(*)[68])(sm + 3 * 64 * 68);

    const int b = blockIdx.z, h = blockIdx.y, qt = blockIdx.x;
    const int tid = threadIdx.x;
    const int tx = tid & 15;
    const int ty = tid >> 4;
    const float scale = 0.125f;   // HD^-0.5

    const float* qbase = qkv + ((size_t)b * LL + qt * 64) * E3 + h * HD;
    const float* kbase = qkv + (size_t)b * LL * E3 + DD + h * HD;
    const float* vbase = qkv + (size_t)b * LL * E3 + 2 * DD + h * HD;

    // Load Q tile transposed: Qs[d][r]. Lanes take consecutive r -> clean STS.
    {
        int r = tid & 63;
        int cb = (tid >> 6) * 16;
        #pragma unroll
        for (int p4 = 0; p4 < 4; p4++) {
            int c = cb + p4 * 4;
            float4 v = *(const float4*)(qbase + (size_t)r * E3 + c);
            Qs[c + 0][r] = v.x; Qs[c + 1][r] = v.y;
            Qs[c + 2][r] = v.z; Qs[c + 3][r] = v.w;
        }
    }

    float m_i[4], l_i[4], o_acc[4][4];
    #pragma unroll
    for (int i = 0; i < 4; i++) {
        m_i[i] = -1e30f; l_i[i] = 0.f;
        #pragma unroll
        for (int j = 0; j < 4; j++) o_acc[i][j] = 0.f;
    }

    for (int kt = 0; kt < LL / 64; kt++) {
        __syncthreads();   // previous iteration done with Ks/Vs/Ps (covers Q load on kt=0)
        // K tile transposed
        {
            int r = tid & 63;
            const float* kr = kbase + ((size_t)kt * 64 + r) * E3;
            int cb = (tid >> 6) * 16;
            #pragma unroll
            for (int p4 = 0; p4 < 4; p4++) {
                int c = cb + p4 * 4;
                float4 v = *(const float4*)(kr + c);
                Ks[c + 0][r] = v.x; Ks[c + 1][r] = v.y;
                Ks[c + 2][r] = v.z; Ks[c + 3][r] = v.w;
            }
        }
        // V tile natural layout
        for (int i = tid; i < 64 * 16; i += 256) {
            int r = i >> 4, c = (i & 15) * 4;
            float4 v = *(const float4*)(vbase + ((size_t)kt * 64 + r) * E3 + c);
            *(float4*)&Vs[r][c] = v;
        }
        __syncthreads();

        // S = scale * Q K^T   (4x4 per thread)
        float s[4][4] = {};
        #pragma unroll 8
        for (int d = 0; d < 64; d++) {
            float qa[4], kb[4];
            *(float4*)qa = *(const float4*)&Qs[d][ty * 4];
            *(float4*)kb = *(const float4*)&Ks[d][tx * 4];
            #pragma unroll
            for (int i = 0; i < 4; i++)
                #pragma unroll
                for (int j = 0; j < 4; j++)
                    s[i][j] = fmaf(qa[i], kb[j], s[i][j]);
        }

        // online softmax
        float mt[4], rs[4], sf[4];
        #pragma unroll
        for (int i = 0; i < 4; i++) {
            float m0 = fmaxf(fmaxf(s[i][0], s[i][1]), fmaxf(s[i][2], s[i][3]));
            mt[i] = m0 * 1.0f;
        }
        #pragma unroll
        for (int i = 0; i < 4; i++) {
            #pragma unroll
            for (int j = 0; j < 4; j++) s[i][j] *= scale;
            mt[i] *= scale;
        }
        #pragma unroll
        for (int off = 8; off >= 1; off >>= 1)
            #pragma unroll
            for (int i = 0; i < 4; i++)
                mt[i] = fmaxf(mt[i], __shfl_xor_sync(0xffffffffu, mt[i], off));
        #pragma unroll
        for (int i = 0; i < 4; i++) {
            float mnew = fmaxf(m_i[i], mt[i]);
            rs[i] = 0.f;
            #pragma unroll
            for (int j = 0; j < 4; j++) {
                s[i][j] = __expf(s[i][j] - mnew);
                rs[i] += s[i][j];
            }
            sf[i] = __expf(m_i[i] - mnew);
            m_i[i] = mnew;
        }
        #pragma unroll
        for (int off = 8; off >= 1; off >>= 1)
            #pragma unroll
            for (int i = 0; i < 4; i++)
                rs[i] += __shfl_xor_sync(0xffffffffu, rs[i], off);
        #pragma unroll
        for (int i = 0; i < 4; i++) {
            l_i[i] = l_i[i] * sf[i] + rs[i];
            #pragma unroll
            for (int j = 0; j < 4; j++) o_acc[i][j] *= sf[i];
        }
        // stage P
        #pragma unroll
        for (int i = 0; i < 4; i++)
            *(float4*)&Ps[ty * 4 + i][tx * 4] = make_float4(s[i][0], s[i][1], s[i][2], s[i][3]);
        __syncthreads();

        // O += P @ V
        #pragma unroll 4
        for (int kk4 = 0; kk4 < 64; kk4 += 4) {
            float pr[4][4];
            #pragma unroll
            for (int i = 0; i < 4; i++)
                *(float4*)pr[i] = *(const float4*)&Ps[ty * 4 + i][kk4];
            #pragma unroll
            for (int u = 0; u < 4; u++) {
                float vv[4];
                *(float4*)vv = *(const float4*)&Vs[kk4 + u][tx * 4];
                #pragma unroll
                for (int i = 0; i < 4; i++)
                    #pragma unroll
                    for (int j = 0; j < 4; j++)
                        o_acc[i][j] = fmaf(pr[i][u], vv[j], o_acc[i][j]);
            }
        }
    }

    // epilogue: normalize and write (b,l,h,hd)
    #pragma unroll
    for (int i = 0; i < 4; i++) {
        float inv = 1.0f / l_i[i];
        size_t row = (size_t)b * LL + qt * 64 + ty * 4 + i;
        float* orow = O + row * DD + h * HD + tx * 4;
        #pragma unroll
        for (int j = 0; j < 4; j++) orow[j] = o_acc[i][j] * inv;
    }
}

// ---------------------------------------------------------------------------
extern "C" void kernel_launch(void* const* d_in, const int* in_sizes, int n_in,
                              void* d_out, int out_size)
{
    const float* x     = (const float*)d_in[0];
    const float* p     = (const float*)d_in[1];
    const float* W_qkv = (const float*)d_in[2];
    const float* b_qkv = (const float*)d_in[3];
    const float* W_out = (const float*)d_in[4];
    const float* b_out = (const float*)d_in[5];
    const float* proj  = (const float*)d_in[6];
    float* out = (float*)d_out;

    float *qkv, *phases, *o, *projT;
    cudaGetSymbolAddress((void**)&qkv,    g_qkv);
    cudaGetSymbolAddress((void**)&phases, g_phases);
    cudaGetSymbolAddress((void**)&o,      g_o);
    cudaGetSymbolAddress((void**)&projT,  g_projT);

    // 1. transpose proj -> (PH, D)
    transpose_proj<<<(DD * PH) / 256, 256>>>(proj, projT);

    // 2. QKV GEMM: (4096,3072) = x(4096,1024) @ W_qkv(3072,1024)^T + b
    gemm_nt_64x64<<<dim3(E3 / 64, MM / 64), 256>>>(x, W_qkv, b_qkv, qkv, MM, E3, DD);

    // 3. phases GEMM: (4096,512) = p @ projT^T
    gemm_nt_64x64<<<dim3(PH / 64, MM / 64), 256>>>(p, projT, nullptr, phases, MM, PH, DD);

    // 4. rotate q,k in place
    rope_rot<<<(MM * PH) / 256, 256>>>(qkv, phases);

    // 5. flash attention -> g_o (b,l,h,hd)
    cudaFuncSetAttribute(flash_attn, cudaFuncAttributeMaxDynamicSharedMemorySize, FLASH_SMEM);
    flash_attn<<<dim3(LL / 64, HH, BB), 256, FLASH_SMEM>>>(qkv, o);

    // 6. output GEMM: (4096,1024) = o @ W_out(1024,1024)^T + b_out
    gemm_nt_64x64<<<dim3(DD / 64, MM / 64), 256>>>(o, W_out, b_out, out, MM, DD, DD);
}

// round 2
// speedup vs baseline: 1.0364x; 1.0364x over previous
#include <cuda_runtime.h>
#include <cuda_bf16.h>
#include <cstdint>

// Problem constants
#define BB 2
#define LL 2048
#define DD 1024
#define HH 16
#define HD 64
#define MM (BB*LL)          // 4096 rows
#define E3 (3*DD)           // 3072
#define PH (DD/2)           // 512 phase dims

typedef unsigned long long ull;

// Scratch (device globals; no runtime allocation allowed)
__device__ float g_qkv[MM * E3];          // 50 MB
__device__ float g_phases[MM * PH];       // 8 MB
__device__ float g_o[MM * DD];            // 16 MB
__device__ float g_projT[PH * DD];        // 2 MB

// ---------------------------------------------------------------------------
// Packed f32x2 helpers (FFMA2 path — ptxas never emits these from C++)
// ---------------------------------------------------------------------------
union Fl4 { float4 f; ull u[2]; };

__device__ __forceinline__ ull pack_dup(float v) {
    ull r;
    asm("mov.b64 %0, {%1, %1};" : "=l"(r) : "f"(v));
    return r;
}
__device__ __forceinline__ void ffma2(ull& d, ull a, ull b) {
    asm("fma.rn.f32x2 %0, %1, %2, %0;" : "+l"(d) : "l"(a), "l"(b));
}
__device__ __forceinline__ void fmul2(ull& d, ull a) {
    asm("mul.rn.f32x2 %0, %0, %1;" : "+l"(d) : "l"(a));
}
__device__ __forceinline__ float2 unpack2(ull v) {
    float2 r;
    asm("mov.b64 {%0, %1}, %2;" : "=f"(r.x), "=f"(r.y) : "l"(v));
    return r;
}

// ---------------------------------------------------------------------------
// NT GEMM: C[M,N] = A[M,K] @ B[N,K]^T (+ bias[N])
// 64x64 tile, BK=16, 256 threads, 4x4 per thread, double-buffered smem,
// packed f32x2 accumulation.
// ---------------------------------------------------------------------------
__global__ __launch_bounds__(256) void gemm_nt_64x64(
    const float* __restrict__ A, const float* __restrict__ Bm,
    const float* __restrict__ bias, float* __restrict__ C,
    int M, int N, int K)
{
    __shared__ float As[2][16][68];
    __shared__ float Bs[2][16][68];
    const int tid = threadIdx.x;
    const int bm = blockIdx.y * 64;
    const int bn = blockIdx.x * 64;
    const int tx = tid & 15;
    const int ty = tid >> 4;
    const int lr = tid >> 2;          // 0..63 tile row
    const int lc = (tid & 3) << 2;    // 0,4,8,12 within BK

    const float* Aptr = A + (size_t)(bm + lr) * K + lc;
    const float* Bptr = Bm + (size_t)(bn + lr) * K + lc;

    ull acc2[4][2] = {};   // bitwise zero == (0.f, 0.f)

    // prologue: fill buffer 0
    {
        float4 av = *(const float4*)(Aptr);
        float4 bv = *(const float4*)(Bptr);
        As[0][lc + 0][lr] = av.x; As[0][lc + 1][lr] = av.y;
        As[0][lc + 2][lr] = av.z; As[0][lc + 3][lr] = av.w;
        Bs[0][lc + 0][lr] = bv.x; Bs[0][lc + 1][lr] = bv.y;
        Bs[0][lc + 2][lr] = bv.z; Bs[0][lc + 3][lr] = bv.w;
    }
    __syncthreads();

    int cur = 0;
    for (int k0 = 0; k0 < K; k0 += 16) {
        const bool has_next = (k0 + 16) < K;
        float4 av, bv;
        if (has_next) {
            av = *(const float4*)(Aptr + k0 + 16);
            bv = *(const float4*)(Bptr + k0 + 16);
        }
        #pragma unroll
        for (int kk = 0; kk < 16; kk++) {
            float ar[4];
            *(float4*)ar = *(const float4*)&As[cur][kk][ty * 4];
            Fl4 bu;
            bu.f = *(const float4*)&Bs[cur][kk][tx * 4];
            #pragma unroll
            for (int i = 0; i < 4; i++) {
                ull ad = pack_dup(ar[i]);
                ffma2(acc2[i][0], ad, bu.u[0]);
                ffma2(acc2[i][1], ad, bu.u[1]);
            }
        }
        if (has_next) {
            const int nb = cur ^ 1;
            As[nb][lc + 0][lr] = av.x; As[nb][lc + 1][lr] = av.y;
            As[nb][lc + 2][lr] = av.z; As[nb][lc + 3][lr] = av.w;
            Bs[nb][lc + 0][lr] = bv.x; Bs[nb][lc + 1][lr] = bv.y;
            Bs[nb][lc + 2][lr] = bv.z; Bs[nb][lc + 3][lr] = bv.w;
            __syncthreads();
            cur = nb;
        }
    }

    #pragma unroll
    for (int i = 0; i < 4; i++) {
        const size_t row = bm + ty * 4 + i;
        float2 v01 = unpack2(acc2[i][0]);
        float2 v23 = unpack2(acc2[i][1]);
        float v[4] = {v01.x, v01.y, v23.x, v23.y};
        #pragma unroll
        for (int j = 0; j < 4; j++) {
            const int col = bn + tx * 4 + j;
            float o = v[j];
            if (bias) o += bias[col];
            C[row * N + col] = o;
        }
    }
}

// ---------------------------------------------------------------------------
// proj (D, PH) row-major -> projT (PH, D)
// ---------------------------------------------------------------------------
__global__ void transpose_proj(const float* __restrict__ P, float* __restrict__ PT)
{
    int idx = blockIdx.x * blockDim.x + threadIdx.x;
    int d = idx >> 9;
    int j = idx & 511;
    PT[(size_t)j * DD + d] = P[idx];
}

// ---------------------------------------------------------------------------
// In-place rotation of q and k inside the qkv buffer.
// ---------------------------------------------------------------------------
__global__ void rope_rot(float* __restrict__ qkv, const float* __restrict__ phases)
{
    int idx = blockIdx.x * blockDim.x + threadIdx.x;   // MM*PH threads
    int m = idx >> 9;
    int r = idx & 511;
    int h = r >> 5;
    int j = r & 31;
    float ph = phases[idx];
    float s, c;
    __sincosf(ph, &s, &c);
    size_t base = (size_t)m * E3 + h * HD + j;
    float q1 = qkv[base], q2 = qkv[base + 32];
    qkv[base]        = q1 * c - q2 * s;
    qkv[base + 32]   = q1 * s + q2 * c;
    float k1 = qkv[base + DD], k2 = qkv[base + DD + 32];
    qkv[base + DD]      = k1 * c - k2 * s;
    qkv[base + DD + 32] = k1 * s + k2 * c;
}

// ---------------------------------------------------------------------------
// Flash attention. grid = (L/64, H, B), 256 threads, packed f32x2 math.
// ---------------------------------------------------------------------------
#define FLASH_SMEM (4 * 64 * 68 * 4)

__global__ __launch_bounds__(256) void flash_attn(
    const float* __restrict__ qkv, float* __restrict__ O)
{
    extern __shared__ float sm[];
    float (*Qs)[68] = (float(*)[68])(sm);
    float (*Ks)[68] = (float(*)[68])(sm + 64 * 68);
    float (*Vs)[68] = (float(*)[68])(sm + 2 * 64 * 68);
    float (*Ps)[68] = (float(*)[68])(sm + 3 * 64 * 68);

    const int b = blockIdx.z, h = blockIdx.y, qt = blockIdx.x;
    const int tid = threadIdx.x;
    const int tx = tid & 15;
    const int ty = tid >> 4;
    const float scale = 0.125f;   // HD^-0.5

    const float* qbase = qkv + ((size_t)b * LL + qt * 64) * E3 + h * HD;
    const float* kbase = qkv + (size_t)b * LL * E3 + DD + h * HD;
    const float* vbase = qkv + (size_t)b * LL * E3 + 2 * DD + h * HD;

    // Load Q tile transposed: Qs[d][r]
    {
        int r = tid & 63;
        int cb = (tid >> 6) * 16;
        #pragma unroll
        for (int p4 = 0; p4 < 4; p4++) {
            int c = cb + p4 * 4;
            float4 v = *(const float4*)(qbase + (size_t)r * E3 + c);
            Qs[c + 0][r] = v.x; Qs[c + 1][r] = v.y;
            Qs[c + 2][r] = v.z; Qs[c + 3][r] = v.w;
        }
    }

    float m_i[4], l_i[4];
    ull o2[4][2] = {};
    #pragma unroll
    for (int i = 0; i < 4; i++) { m_i[i] = -1e30f; l_i[i] = 0.f; }

    for (int kt = 0; kt < LL / 64; kt++) {
        __syncthreads();
        // K tile transposed
        {
            int r = tid & 63;
            const float* kr = kbase + ((size_t)kt * 64 + r) * E3;
            int cb = (tid >> 6) * 16;
            #pragma unroll
            for (int p4 = 0; p4 < 4; p4++) {
                int c = cb + p4 * 4;
                float4 v = *(const float4*)(kr + c);
                Ks[c + 0][r] = v.x; Ks[c + 1][r] = v.y;
                Ks[c + 2][r] = v.z; Ks[c + 3][r] = v.w;
            }
        }
        // V tile natural layout
        for (int i = tid; i < 64 * 16; i += 256) {
            int r = i >> 4, c = (i & 15) * 4;
            float4 v = *(const float4*)(vbase + ((size_t)kt * 64 + r) * E3 + c);
            *(float4*)&Vs[r][c] = v;
        }
        __syncthreads();

        // S = Q K^T (packed)
        ull s2[4][2] = {};
        #pragma unroll 8
        for (int d = 0; d < 64; d++) {
            float qa[4];
            *(float4*)qa = *(const float4*)&Qs[d][ty * 4];
            Fl4 kb;
            kb.f = *(const float4*)&Ks[d][tx * 4];
            #pragma unroll
            for (int i = 0; i < 4; i++) {
                ull ad = pack_dup(qa[i]);
                ffma2(s2[i][0], ad, kb.u[0]);
                ffma2(s2[i][1], ad, kb.u[1]);
            }
        }

        // unpack and scale
        float s[4][4];
        #pragma unroll
        for (int i = 0; i < 4; i++) {
            float2 a = unpack2(s2[i][0]);
            float2 bq = unpack2(s2[i][1]);
            s[i][0] = a.x * scale; s[i][1] = a.y * scale;
            s[i][2] = bq.x * scale; s[i][3] = bq.y * scale;
        }

        // online softmax
        float mt[4], rs[4], sf[4];
        #pragma unroll
        for (int i = 0; i < 4; i++)
            mt[i] = fmaxf(fmaxf(s[i][0], s[i][1]), fmaxf(s[i][2], s[i][3]));
        #pragma unroll
        for (int off = 8; off >= 1; off >>= 1)
            #pragma unroll
            for (int i = 0; i < 4; i++)
                mt[i] = fmaxf(mt[i], __shfl_xor_sync(0xffffffffu, mt[i], off));
        #pragma unroll
        for (int i = 0; i < 4; i++) {
            float mnew = fmaxf(m_i[i], mt[i]);
            rs[i] = 0.f;
            #pragma unroll
            for (int j = 0; j < 4; j++) {
                s[i][j] = __expf(s[i][j] - mnew);
                rs[i] += s[i][j];
            }
            sf[i] = __expf(m_i[i] - mnew);
            m_i[i] = mnew;
        }
        #pragma unroll
        for (int off = 8; off >= 1; off >>= 1)
            #pragma unroll
            for (int i = 0; i < 4; i++)
                rs[i] += __shfl_xor_sync(0xffffffffu, rs[i], off);
        #pragma unroll
        for (int i = 0; i < 4; i++) {
            l_i[i] = l_i[i] * sf[i] + rs[i];
            ull sfd = pack_dup(sf[i]);
            fmul2(o2[i][0], sfd);
            fmul2(o2[i][1], sfd);
        }
        // stage P
        #pragma unroll
        for (int i = 0; i < 4; i++)
            *(float4*)&Ps[ty * 4 + i][tx * 4] = make_float4(s[i][0], s[i][1], s[i][2], s[i][3]);
        __syncthreads();

        // O += P @ V (packed)
        #pragma unroll 4
        for (int kk4 = 0; kk4 < 64; kk4 += 4) {
            float pr[4][4];
            #pragma unroll
            for (int i = 0; i < 4; i++)
                *(float4*)pr[i] = *(const float4*)&Ps[ty * 4 + i][kk4];
            #pragma unroll
            for (int u = 0; u < 4; u++) {
                Fl4 vv;
                vv.f = *(const float4*)&Vs[kk4 + u][tx * 4];
                #pragma unroll
                for (int i = 0; i < 4; i++) {
                    ull pd = pack_dup(pr[i][u]);
                    ffma2(o2[i][0], pd, vv.u[0]);
                    ffma2(o2[i][1], pd, vv.u[1]);
                }
            }
        }
    }

    // epilogue: normalize and write (b,l,h,hd)
    #pragma unroll
    for (int i = 0; i < 4; i++) {
        float inv = 1.0f / l_i[i];
        size_t row = (size_t)b * LL + qt * 64 + ty * 4 + i;
        float* orow = O + row * DD + h * HD + tx * 4;
        float2 a = unpack2(o2[i][0]);
        float2 bq = unpack2(o2[i][1]);
        orow[0] = a.x * inv;  orow[1] = a.y * inv;
        orow[2] = bq.x * inv; orow[3] = bq.y * inv;
    }
}

// ---------------------------------------------------------------------------
extern "C" void kernel_launch(void* const* d_in, const int* in_sizes, int n_in,
                              void* d_out, int out_size)
{
    const float* x     = (const float*)d_in[0];
    const float* p     = (const float*)d_in[1];
    const float* W_qkv = (const float*)d_in[2];
    const float* b_qkv = (const float*)d_in[3];
    const float* W_out = (const float*)d_in[4];
    const float* b_out = (const float*)d_in[5];
    const float* proj  = (const float*)d_in[6];
    float* out = (float*)d_out;

    float *qkv, *phases, *o, *projT;
    cudaGetSymbolAddress((void**)&qkv,    g_qkv);
    cudaGetSymbolAddress((void**)&phases, g_phases);
    cudaGetSymbolAddress((void**)&o,      g_o);
    cudaGetSymbolAddress((void**)&projT,  g_projT);

    transpose_proj<<<(DD * PH) / 256, 256>>>(proj, projT);

    gemm_nt_64x64<<<dim3(E3 / 64, MM / 64), 256>>>(x, W_qkv, b_qkv, qkv, MM, E3, DD);

    gemm_nt_64x64<<<dim3(PH / 64, MM / 64), 256>>>(p, projT, nullptr, phases, MM, PH, DD);

    rope_rot<<<(MM * PH) / 256, 256>>>(qkv, phases);

    cudaFuncSetAttribute(flash_attn, cudaFuncAttributeMaxDynamicSharedMemorySize, FLASH_SMEM);
    flash_attn<<<dim3(LL / 64, HH, BB), 256, FLASH_SMEM>>>(qkv, o);

    gemm_nt_64x64<<<dim3(DD / 64, MM / 64), 256>>>(o, W_out, b_out, out, MM, DD, DD);
}

// round 6
// speedup vs baseline: 1.4182x; 1.3683x over previous
#include <cuda_runtime.h>
#include <cuda_bf16.h>
#include <cstdint>

#define BB 2
#define LL 2048
#define DD 1024
#define HH 16
#define HD 64
#define MM (BB*LL)          // 4096
#define E3 (3*DD)           // 3072
#define PH (DD/2)           // 512
#define GK DD               // all GEMMs K=1024

typedef unsigned long long ull;

// ---------------- scratch ----------------
__device__ float g_qkv[MM * E3];
__device__ float g_phases[MM * PH];
__device__ float g_o[MM * DD];
__device__ float g_projT[PH * DD];
__device__ __nv_bfloat16 g_xh[MM*DD],  g_xl[MM*DD];
__device__ __nv_bfloat16 g_wqh[E3*DD], g_wql[E3*DD];
__device__ __nv_bfloat16 g_ph2[MM*DD], g_pl2[MM*DD];
__device__ __nv_bfloat16 g_pth[PH*DD], g_ptl[PH*DD];
__device__ __nv_bfloat16 g_oh[MM*DD],  g_ol[MM*DD];
__device__ __nv_bfloat16 g_woh[DD*DD], g_wol[DD*DD];

// ---------------- PTX helpers (arch-agnostic: sm_80+ ISA only) ----------------
__device__ __forceinline__ uint32_t smem_u32(const void* p) {
    uint32_t a;
    asm("{ .reg .u64 t; cvta.to.shared.u64 t, %1; cvt.u32.u64 %0, t; }" : "=r"(a) : "l"(p));
    return a;
}
#define LDSM4(R, addr) \
    asm volatile("ldmatrix.sync.aligned.m8n8.x4.shared.b16 {%0,%1,%2,%3}, [%4];" \
        : "=r"((R)[0]), "=r"((R)[1]), "=r"((R)[2]), "=r"((R)[3]) : "r"(addr))
#define MMA16816(D, A, B0, B1) \
    asm volatile("mma.sync.aligned.m16n8k16.row.col.f32.bf16.bf16.f32 " \
        "{%0,%1,%2,%3}, {%4,%5,%6,%7}, {%8,%9}, {%0,%1,%2,%3};" \
        : "+f"((D)[0]), "+f"((D)[1]), "+f"((D)[2]), "+f"((D)[3]) \
        : "r"((A)[0]), "r"((A)[1]), "r"((A)[2]), "r"((A)[3]), "r"(B0), "r"(B1))
#define CPA16(dst, src) \
    asm volatile("cp.async.cg.shared.global [%0], [%1], 16;" :: "r"(dst), "l"(src))
#define CPA_COMMIT() asm volatile("cp.async.commit_group;" ::: "memory")
#define CPA_WAIT1()  asm volatile("cp.async.wait_group 1;" ::: "memory")
#define CPA_WAIT0()  asm volatile("cp.async.wait_group 0;" ::: "memory")

// ---------------------------------------------------------------------------
// fp32 -> (hi, lo) bf16 split
// ---------------------------------------------------------------------------
__global__ void split_bf16(const float* __restrict__ src,
                           __nv_bfloat16* __restrict__ hi, __nv_bfloat16* __restrict__ lo, int n)
{
    int i = blockIdx.x * blockDim.x + threadIdx.x;
    if (i < n) {
        float v = src[i];
        __nv_bfloat16 h = __float2bfloat16(v);
        hi[i] = h;
        lo[i] = __float2bfloat16(v - __bfloat162float(h));
    }
}

// ---------------------------------------------------------------------------
// HMMA NT GEMM: C[M,N] = A[M,K] @ B[N,K]^T (+bias). K = 1024.
// 128x128 block tile, BK=32, 256 threads (8 warps = 4Mx2N), warp tile 32x64.
// bf16 hi/lo 3-term split accumulated in fp32. cp.async double-buffered.
// smem per stage: Ahi, Alo, Bhi, Blo each [128][40] bf16 (pitch 40 = pad 8).
// ---------------------------------------------------------------------------
#define PITCH 40
#define BUF_B (128 * PITCH * 2)         // 10240 B per operand buffer
#define STAGE_B (4 * BUF_B)             // 40960 B per stage
#define GEMM_SMEM (2 * STAGE_B)         // 81920 B
#define NKC (GK / 32)                   // 32 k-chunks

__global__ __launch_bounds__(256) void gemm_mma(
    const __nv_bfloat16* __restrict__ Ahi, const __nv_bfloat16* __restrict__ Alo,
    const __nv_bfloat16* __restrict__ Bhi, const __nv_bfloat16* __restrict__ Blo,
    const float* __restrict__ bias, float* __restrict__ C, int N)
{
    extern __shared__ char smem[];
    const uint32_t sb = smem_u32(smem);
    const int tid = threadIdx.x;
    const int lane = tid & 31;
    const int wid = tid >> 5;
    const int warp_m = wid >> 1;          // 0..3
    const int warp_n = wid & 1;           // 0..1
    const int bm = blockIdx.y * 128;
    const int bn = blockIdx.x * 128;

    // loader role: thread t covers (row = t>>1, khalf = t&1) — 16 bf16 = 32B
    const int lr = tid >> 1;
    const int lh = tid & 1;
    const __nv_bfloat16* gAh = Ahi + (size_t)(bm + lr) * GK + lh * 16;
    const __nv_bfloat16* gAl = Alo + (size_t)(bm + lr) * GK + lh * 16;
    const __nv_bfloat16* gBh = Bhi + (size_t)(bn + lr) * GK + lh * 16;
    const __nv_bfloat16* gBl = Blo + (size_t)(bn + lr) * GK + lh * 16;
    const uint32_t srow = sb + (uint32_t)(lr * PITCH + lh * 16) * 2;

    auto issue_stage = [&](int kc, int s) {
        const uint32_t st = srow + s * STAGE_B;
        const size_t go = (size_t)kc * 32;
        CPA16(st + 0 * BUF_B,      gAh + go);
        CPA16(st + 0 * BUF_B + 16, gAh + go + 8);
        CPA16(st + 1 * BUF_B,      gAl + go);
        CPA16(st + 1 * BUF_B + 16, gAl + go + 8);
        CPA16(st + 2 * BUF_B,      gBh + go);
        CPA16(st + 2 * BUF_B + 16, gBh + go + 8);
        CPA16(st + 3 * BUF_B,      gBl + go);
        CPA16(st + 3 * BUF_B + 16, gBl + go + 8);
    };

    float acc[2][8][4];
    #pragma unroll
    for (int mt = 0; mt < 2; mt++)
        #pragma unroll
        for (int nt = 0; nt < 8; nt++)
            #pragma unroll
            for (int e = 0; e < 4; e++) acc[mt][nt][e] = 0.f;

    // ldmatrix base offsets (per-lane)
    const int lrow = lane & 15;           // matrix row within 16
    const int lsub = lane >> 4;           // 0/1 -> +8 cols
    // A rows: warp_m*32 + mt*16 + lrow ; cols: h*16 + lsub*8
    // B rows: warp_n*64 + g*16 + lrow  ; cols: h*16 + lsub*8

    issue_stage(0, 0);
    CPA_COMMIT();

    for (int kc = 0; kc < NKC; kc++) {
        const int cur = kc & 1;
        if (kc + 1 < NKC) {
            issue_stage(kc + 1, cur ^ 1);
            CPA_COMMIT();
            CPA_WAIT1();
        } else {
            CPA_WAIT0();
        }
        __syncthreads();

        const uint32_t stA_hi = sb + cur * STAGE_B;
        const uint32_t stA_lo = stA_hi + BUF_B;
        const uint32_t stB_hi = stA_hi + 2 * BUF_B;
        const uint32_t stB_lo = stA_hi + 3 * BUF_B;

        #pragma unroll
        for (int h = 0; h < 2; h++) {
            const uint32_t coff = (uint32_t)(h * 16 + lsub * 8) * 2;
            uint32_t ah[2][4], al[2][4];
            #pragma unroll
            for (int mt = 0; mt < 2; mt++) {
                const uint32_t ro = (uint32_t)((warp_m * 32 + mt * 16 + lrow) * PITCH) * 2 + coff;
                LDSM4(ah[mt], stA_hi + ro);
                LDSM4(al[mt], stA_lo + ro);
            }
            uint32_t bh[4][4], bl[4][4];
            #pragma unroll
            for (int g = 0; g < 4; g++) {
                const uint32_t ro = (uint32_t)((warp_n * 64 + g * 16 + lrow) * PITCH) * 2 + coff;
                LDSM4(bh[g], stB_hi + ro);
                LDSM4(bl[g], stB_lo + ro);
            }
            #pragma unroll
            for (int mt = 0; mt < 2; mt++)
                #pragma unroll
                for (int g = 0; g < 4; g++)
                    #pragma unroll
                    for (int s2 = 0; s2 < 2; s2++) {
                        const int nt = g * 2 + s2;
                        MMA16816(acc[mt][nt], ah[mt], bh[g][s2], bh[g][s2 + 2]);
                        MMA16816(acc[mt][nt], ah[mt], bl[g][s2], bl[g][s2 + 2]);
                        MMA16816(acc[mt][nt], al[mt], bh[g][s2], bh[g][s2 + 2]);
                    }
        }
        __syncthreads();
    }

    // epilogue
    const int gid = lane >> 2;            // 0..7
    const int tig = lane & 3;             // 0..3
    #pragma unroll
    for (int mt = 0; mt < 2; mt++) {
        const int r0 = bm + warp_m * 32 + mt * 16 + gid;
        #pragma unroll
        for (int nt = 0; nt < 8; nt++) {
            const int c0 = bn + warp_n * 64 + nt * 8 + tig * 2;
            float b0 = bias ? bias[c0] : 0.f;
            float b1 = bias ? bias[c0 + 1] : 0.f;
            *(float2*)&C[(size_t)r0 * N + c0] =
                make_float2(acc[mt][nt][0] + b0, acc[mt][nt][1] + b1);
            *(float2*)&C[(size_t)(r0 + 8) * N + c0] =
                make_float2(acc[mt][nt][2] + b0, acc[mt][nt][3] + b1);
        }
    }
}

// ---------------------------------------------------------------------------
__global__ void transpose_proj(const float* __restrict__ P, float* __restrict__ PT)
{
    int idx = blockIdx.x * blockDim.x + threadIdx.x;
    int dd = idx >> 9;
    int j = idx & 511;
    PT[(size_t)j * DD + dd] = P[idx];
}

__global__ void rope_rot(float* __restrict__ qkv, const float* __restrict__ phases)
{
    int idx = blockIdx.x * blockDim.x + threadIdx.x;
    int m = idx >> 9;
    int r = idx & 511;
    int h = r >> 5;
    int j = r & 31;
    float ph = phases[idx];
    float s, c;
    __sincosf(ph, &s, &c);
    size_t base = (size_t)m * E3 + h * HD + j;
    float q1 = qkv[base], q2 = qkv[base + 32];
    qkv[base]        = q1 * c - q2 * s;
    qkv[base + 32]   = q1 * s + q2 * c;
    float k1 = qkv[base + DD], k2 = qkv[base + DD + 32];
    qkv[base + DD]      = k1 * c - k2 * s;
    qkv[base + DD + 32] = k1 * s + k2 * c;
}

// ---------------------------------------------------------------------------
// Flash attention (fp32 SIMT, packed f32x2) — unchanged
// ---------------------------------------------------------------------------
union Fl4 { float4 f; ull u[2]; };
__device__ __forceinline__ ull pack_dup(float v) {
    ull r; asm("mov.b64 %0, {%1, %1};" : "=l"(r) : "f"(v)); return r;
}
__device__ __forceinline__ void ffma2(ull& d, ull a, ull b) {
    asm("fma.rn.f32x2 %0, %1, %2, %0;" : "+l"(d) : "l"(a), "l"(b));
}
__device__ __forceinline__ void fmul2(ull& d, ull a) {
    asm("mul.rn.f32x2 %0, %0, %1;" : "+l"(d) : "l"(a));
}
__device__ __forceinline__ float2 unpack2(ull v) {
    float2 r; asm("mov.b64 {%0, %1}, %2;" : "=f"(r.x), "=f"(r.y) : "l"(v)); return r;
}

#define FLASH_SMEM (4 * 64 * 68 * 4)

__global__ __launch_bounds__(256) void flash_attn(
    const float* __restrict__ qkv, float* __restrict__ O)
{
    extern __shared__ float sm[];
    float (*Qs)[68] = (float(*)[68])(sm);
    float (*Ks)[68] = (float(*)[68])(sm + 64 * 68);
    float (*Vs)[68] = (float(*)[68])(sm + 2 * 64 * 68);
    float (*Ps)[68] = (float(*)[68])(sm + 3 * 64 * 68);

    const int b = blockIdx.z, h = blockIdx.y, qt = blockIdx.x;
    const int tid = threadIdx.x;
    const int tx = tid & 15;
    const int ty = tid >> 4;
    const float scale = 0.125f;

    const float* qbase = qkv + ((size_t)b * LL + qt * 64) * E3 + h * HD;
    const float* kbase = qkv + (size_t)b * LL * E3 + DD + h * HD;
    const float* vbase = qkv + (size_t)b * LL * E3 + 2 * DD + h * HD;

    {
        int r = tid & 63;
        int cb = (tid >> 6) * 16;
        #pragma unroll
        for (int p4 = 0; p4 < 4; p4++) {
            int c = cb + p4 * 4;
            float4 v = *(const float4*)(qbase + (size_t)r * E3 + c);
            Qs[c + 0][r] = v.x; Qs[c + 1][r] = v.y;
            Qs[c + 2][r] = v.z; Qs[c + 3][r] = v.w;
        }
    }

    float m_i[4], l_i[4];
    ull o2[4][2] = {};
    #pragma unroll
    for (int i = 0; i < 4; i++) { m_i[i] = -1e30f; l_i[i] = 0.f; }

    for (int kt = 0; kt < LL / 64; kt++) {
        __syncthreads();
        {
            int r = tid & 63;
            const float* kr = kbase + ((size_t)kt * 64 + r) * E3;
            int cb = (tid >> 6) * 16;
            #pragma unroll
            for (int p4 = 0; p4 < 4; p4++) {
                int c = cb + p4 * 4;
                float4 v = *(const float4*)(kr + c);
                Ks[c + 0][r] = v.x; Ks[c + 1][r] = v.y;
                Ks[c + 2][r] = v.z; Ks[c + 3][r] = v.w;
            }
        }
        for (int i = tid; i < 64 * 16; i += 256) {
            int r = i >> 4, c = (i & 15) * 4;
            float4 v = *(const float4*)(vbase + ((size_t)kt * 64 + r) * E3 + c);
            *(float4*)&Vs[r][c] = v;
        }
        __syncthreads();

        ull s2[4][2] = {};
        #pragma unroll 8
        for (int dd = 0; dd < 64; dd++) {
            float qa[4];
            *(float4*)qa = *(const float4*)&Qs[dd][ty * 4];
            Fl4 kb;
            kb.f = *(const float4*)&Ks[dd][tx * 4];
            #pragma unroll
            for (int i = 0; i < 4; i++) {
                ull ad = pack_dup(qa[i]);
                ffma2(s2[i][0], ad, kb.u[0]);
                ffma2(s2[i][1], ad, kb.u[1]);
            }
        }

        float s[4][4];
        #pragma unroll
        for (int i = 0; i < 4; i++) {
            float2 a = unpack2(s2[i][0]);
            float2 bq = unpack2(s2[i][1]);
            s[i][0] = a.x * scale; s[i][1] = a.y * scale;
            s[i][2] = bq.x * scale; s[i][3] = bq.y * scale;
        }

        float mt[4], rs[4], sf[4];
        #pragma unroll
        for (int i = 0; i < 4; i++)
            mt[i] = fmaxf(fmaxf(s[i][0], s[i][1]), fmaxf(s[i][2], s[i][3]));
        #pragma unroll
        for (int off = 8; off >= 1; off >>= 1)
            #pragma unroll
            for (int i = 0; i < 4; i++)
                mt[i] = fmaxf(mt[i], __shfl_xor_sync(0xffffffffu, mt[i], off));
        #pragma unroll
        for (int i = 0; i < 4; i++) {
            float mnew = fmaxf(m_i[i], mt[i]);
            rs[i] = 0.f;
            #pragma unroll
            for (int j = 0; j < 4; j++) {
                s[i][j] = __expf(s[i][j] - mnew);
                rs[i] += s[i][j];
            }
            sf[i] = __expf(m_i[i] - mnew);
            m_i[i] = mnew;
        }
        #pragma unroll
        for (int off = 8; off >= 1; off >>= 1)
            #pragma unroll
            for (int i = 0; i < 4; i++)
                rs[i] += __shfl_xor_sync(0xffffffffu, rs[i], off);
        #pragma unroll
        for (int i = 0; i < 4; i++) {
            l_i[i] = l_i[i] * sf[i] + rs[i];
            ull sfd = pack_dup(sf[i]);
            fmul2(o2[i][0], sfd);
            fmul2(o2[i][1], sfd);
        }
        #pragma unroll
        for (int i = 0; i < 4; i++)
            *(float4*)&Ps[ty * 4 + i][tx * 4] = make_float4(s[i][0], s[i][1], s[i][2], s[i][3]);
        __syncthreads();

        #pragma unroll 4
        for (int kk4 = 0; kk4 < 64; kk4 += 4) {
            float pr[4][4];
            #pragma unroll
            for (int i = 0; i < 4; i++)
                *(float4*)pr[i] = *(const float4*)&Ps[ty * 4 + i][kk4];
            #pragma unroll
            for (int u = 0; u < 4; u++) {
                Fl4 vv;
                vv.f = *(const float4*)&Vs[kk4 + u][tx * 4];
                #pragma unroll
                for (int i = 0; i < 4; i++) {
                    ull pd = pack_dup(pr[i][u]);
                    ffma2(o2[i][0], pd, vv.u[0]);
                    ffma2(o2[i][1], pd, vv.u[1]);
                }
            }
        }
    }

    #pragma unroll
    for (int i = 0; i < 4; i++) {
        float inv = 1.0f / l_i[i];
        size_t row = (size_t)b * LL + qt * 64 + ty * 4 + i;
        float* orow = O + row * DD + h * HD + tx * 4;
        float2 a = unpack2(o2[i][0]);
        float2 bq = unpack2(o2[i][1]);
        orow[0] = a.x * inv;  orow[1] = a.y * inv;
        orow[2] = bq.x * inv; orow[3] = bq.y * inv;
    }
}

// ---------------------------------------------------------------------------
extern "C" void kernel_launch(void* const* d_in, const int* in_sizes, int n_in,
                              void* d_out, int out_size)
{
    const float* x     = (const float*)d_in[0];
    const float* p     = (const float*)d_in[1];
    const float* W_qkv = (const float*)d_in[2];
    const float* b_qkv = (const float*)d_in[3];
    const float* W_out = (const float*)d_in[4];
    const float* b_out = (const float*)d_in[5];
    const float* proj  = (const float*)d_in[6];
    float* out = (float*)d_out;

    float *qkv, *phases, *o, *projT;
    cudaGetSymbolAddress((void**)&qkv,    g_qkv);
    cudaGetSymbolAddress((void**)&phases, g_phases);
    cudaGetSymbolAddress((void**)&o,      g_o);
    cudaGetSymbolAddress((void**)&projT,  g_projT);
    __nv_bfloat16 *xh, *xl, *wqh, *wql, *ph2, *pl2, *pth, *ptl, *oh, *ol, *woh, *wol;
    cudaGetSymbolAddress((void**)&xh,  g_xh);  cudaGetSymbolAddress((void**)&xl,  g_xl);
    cudaGetSymbolAddress((void**)&wqh, g_wqh); cudaGetSymbolAddress((void**)&wql, g_wql);
    cudaGetSymbolAddress((void**)&ph2, g_ph2); cudaGetSymbolAddress((void**)&pl2, g_pl2);
    cudaGetSymbolAddress((void**)&pth, g_pth); cudaGetSymbolAddress((void**)&ptl, g_ptl);
    cudaGetSymbolAddress((void**)&oh,  g_oh);  cudaGetSymbolAddress((void**)&ol,  g_ol);
    cudaGetSymbolAddress((void**)&woh, g_woh); cudaGetSymbolAddress((void**)&wol, g_wol);

    cudaFuncSetAttribute(gemm_mma, cudaFuncAttributeMaxDynamicSharedMemorySize, GEMM_SMEM);
    cudaFuncSetAttribute(flash_attn, cudaFuncAttributeMaxDynamicSharedMemorySize, FLASH_SMEM);

    transpose_proj<<<(DD * PH) / 256, 256>>>(proj, projT);
    split_bf16<<<(MM * DD) / 256, 256>>>(x, xh, xl, MM * DD);
    split_bf16<<<(E3 * DD) / 256, 256>>>(W_qkv, wqh, wql, E3 * DD);
    split_bf16<<<(MM * DD) / 256, 256>>>(p, ph2, pl2, MM * DD);
    split_bf16<<<(PH * DD) / 256, 256>>>(projT, pth, ptl, PH * DD);

    // QKV GEMM: (4096,3072) = x @ W_qkv^T + b
    gemm_mma<<<dim3(E3 / 128, MM / 128), 256, GEMM_SMEM>>>(xh, xl, wqh, wql, b_qkv, qkv, E3);
    // phases GEMM: (4096,512) = p @ projT^T
    gemm_mma<<<dim3(PH / 128, MM / 128), 256, GEMM_SMEM>>>(ph2, pl2, pth, ptl, nullptr, phases, PH);

    rope_rot<<<(MM * PH) / 256, 256>>>(qkv, phases);

    flash_attn<<<dim3(LL / 64, HH, BB), 256, FLASH_SMEM>>>(qkv, o);

    // out GEMM: (4096,1024) = o @ W_out^T + b_out
    split_bf16<<<(MM * DD) / 256, 256>>>(o, oh, ol, MM * DD);
    split_bf16<<<(DD * DD) / 256, 256>>>(W_out, woh, wol, DD * DD);
    gemm_mma<<<dim3(DD / 128, MM / 128), 256, GEMM_SMEM>>>(oh, ol, woh, wol, b_out, out, DD);
}

// round 7
// speedup vs baseline: 2.0792x; 1.4661x over previous
#include <cuda_runtime.h>
#include <cuda_bf16.h>
#include <cstdint>

#define BB 2
#define LL 2048
#define DD 1024
#define HH 16
#define HD 64
#define MM (BB*LL)          // 4096
#define E3 (3*DD)           // 3072
#define PH (DD/2)           // 512
#define GK DD               // GEMM K=1024

typedef unsigned long long ull;
typedef __nv_bfloat16 bf16;

// ---------------- scratch ----------------
__device__ float g_qkv[MM * E3];
__device__ float g_phases[MM * PH];
__device__ float g_projT[PH * DD];
__device__ bf16 g_xh[MM*DD],  g_xl[MM*DD];
__device__ bf16 g_wqh[E3*DD], g_wql[E3*DD];
__device__ bf16 g_ph2[MM*DD], g_pl2[MM*DD];
__device__ bf16 g_pth[PH*DD], g_ptl[PH*DD];
__device__ bf16 g_oh[MM*DD],  g_ol[MM*DD];
__device__ bf16 g_woh[DD*DD], g_wol[DD*DD];
// attention operands (bf16 hi/lo, layout [m][h*64+d])
__device__ bf16 g_qh[MM*DD], g_ql[MM*DD];
__device__ bf16 g_kh[MM*DD], g_kl[MM*DD];
__device__ bf16 g_vh[MM*DD], g_vl[MM*DD];

// ---------------- PTX helpers (arch-agnostic sm_80+ ISA) ----------------
__device__ __forceinline__ uint32_t smem_u32(const void* p) {
    uint32_t a;
    asm("{ .reg .u64 t; cvta.to.shared.u64 t, %1; cvt.u32.u64 %0, t; }" : "=r"(a) : "l"(p));
    return a;
}
#define LDSM4(R, addr) \
    asm volatile("ldmatrix.sync.aligned.m8n8.x4.shared.b16 {%0,%1,%2,%3}, [%4];" \
        : "=r"((R)[0]), "=r"((R)[1]), "=r"((R)[2]), "=r"((R)[3]) : "r"(addr))
#define LDSM4T(R, addr) \
    asm volatile("ldmatrix.sync.aligned.m8n8.x4.trans.shared.b16 {%0,%1,%2,%3}, [%4];" \
        : "=r"((R)[0]), "=r"((R)[1]), "=r"((R)[2]), "=r"((R)[3]) : "r"(addr))
#define MMA16816(D, A, B0, B1) \
    asm volatile("mma.sync.aligned.m16n8k16.row.col.f32.bf16.bf16.f32 " \
        "{%0,%1,%2,%3}, {%4,%5,%6,%7}, {%8,%9}, {%0,%1,%2,%3};" \
        : "+f"((D)[0]), "+f"((D)[1]), "+f"((D)[2]), "+f"((D)[3]) \
        : "r"((A)[0]), "r"((A)[1]), "r"((A)[2]), "r"((A)[3]), "r"(B0), "r"(B1))
#define CPA16(dst, src) \
    asm volatile("cp.async.cg.shared.global [%0], [%1], 16;" :: "r"(dst), "l"(src))
#define CPA_COMMIT() asm volatile("cp.async.commit_group;" ::: "memory")
#define CPA_WAIT1()  asm volatile("cp.async.wait_group 1;" ::: "memory")
#define CPA_WAIT0()  asm volatile("cp.async.wait_group 0;" ::: "memory")

union BF2U { __nv_bfloat162 b; uint32_t u; };
__device__ __forceinline__ void split_pack2(float e0, float e1, uint32_t& hi, uint32_t& lo) {
    bf16 h0 = __float2bfloat16(e0), h1 = __float2bfloat16(e1);
    float r0 = e0 - __bfloat162float(h0), r1 = e1 - __bfloat162float(h1);
    BF2U a, b2;
    a.b  = __halves2bfloat162(h0, h1);
    b2.b = __halves2bfloat162(__float2bfloat16(r0), __float2bfloat16(r1));
    hi = a.u; lo = b2.u;
}

// ---------------------------------------------------------------------------
// fp32 -> (hi, lo) bf16 split
// ---------------------------------------------------------------------------
__global__ void split_bf16(const float* __restrict__ src,
                           bf16* __restrict__ hi, bf16* __restrict__ lo, int n)
{
    int i = blockIdx.x * blockDim.x + threadIdx.x;
    if (i < n) {
        float v = src[i];
        bf16 h = __float2bfloat16(v);
        hi[i] = h;
        lo[i] = __float2bfloat16(v - __bfloat162float(h));
    }
}

// ---------------------------------------------------------------------------
// HMMA NT GEMM (unchanged from R6): C[M,N] = A @ B^T (+bias), K=1024
// ---------------------------------------------------------------------------
#define PITCH 40
#define BUF_B (128 * PITCH * 2)
#define STAGE_B (4 * BUF_B)
#define GEMM_SMEM (2 * STAGE_B)
#define NKC (GK / 32)

__global__ __launch_bounds__(256) void gemm_mma(
    const bf16* __restrict__ Ahi, const bf16* __restrict__ Alo,
    const bf16* __restrict__ Bhi, const bf16* __restrict__ Blo,
    const float* __restrict__ bias, float* __restrict__ C, int N)
{
    extern __shared__ char smem[];
    const uint32_t sb = smem_u32(smem);
    const int tid = threadIdx.x;
    const int lane = tid & 31;
    const int wid = tid >> 5;
    const int warp_m = wid >> 1;
    const int warp_n = wid & 1;
    const int bm = blockIdx.y * 128;
    const int bn = blockIdx.x * 128;

    const int lr = tid >> 1;
    const int lh = tid & 1;
    const bf16* gAh = Ahi + (size_t)(bm + lr) * GK + lh * 16;
    const bf16* gAl = Alo + (size_t)(bm + lr) * GK + lh * 16;
    const bf16* gBh = Bhi + (size_t)(bn + lr) * GK + lh * 16;
    const bf16* gBl = Blo + (size_t)(bn + lr) * GK + lh * 16;
    const uint32_t srow = sb + (uint32_t)(lr * PITCH + lh * 16) * 2;

    auto issue_stage = [&](int kc, int s) {
        const uint32_t st = srow + s * STAGE_B;
        const size_t go = (size_t)kc * 32;
        CPA16(st + 0 * BUF_B,      gAh + go);
        CPA16(st + 0 * BUF_B + 16, gAh + go + 8);
        CPA16(st + 1 * BUF_B,      gAl + go);
        CPA16(st + 1 * BUF_B + 16, gAl + go + 8);
        CPA16(st + 2 * BUF_B,      gBh + go);
        CPA16(st + 2 * BUF_B + 16, gBh + go + 8);
        CPA16(st + 3 * BUF_B,      gBl + go);
        CPA16(st + 3 * BUF_B + 16, gBl + go + 8);
    };

    float acc[2][8][4];
    #pragma unroll
    for (int mt = 0; mt < 2; mt++)
        #pragma unroll
        for (int nt = 0; nt < 8; nt++)
            #pragma unroll
            for (int e = 0; e < 4; e++) acc[mt][nt][e] = 0.f;

    const int lrow = lane & 15;
    const int lsub = lane >> 4;

    issue_stage(0, 0);
    CPA_COMMIT();

    for (int kc = 0; kc < NKC; kc++) {
        const int cur = kc & 1;
        if (kc + 1 < NKC) {
            issue_stage(kc + 1, cur ^ 1);
            CPA_COMMIT();
            CPA_WAIT1();
        } else {
            CPA_WAIT0();
        }
        __syncthreads();

        const uint32_t stA_hi = sb + cur * STAGE_B;
        const uint32_t stA_lo = stA_hi + BUF_B;
        const uint32_t stB_hi = stA_hi + 2 * BUF_B;
        const uint32_t stB_lo = stA_hi + 3 * BUF_B;

        #pragma unroll
        for (int h = 0; h < 2; h++) {
            const uint32_t coff = (uint32_t)(h * 16 + lsub * 8) * 2;
            uint32_t ah[2][4], al[2][4];
            #pragma unroll
            for (int mt = 0; mt < 2; mt++) {
                const uint32_t ro = (uint32_t)((warp_m * 32 + mt * 16 + lrow) * PITCH) * 2 + coff;
                LDSM4(ah[mt], stA_hi + ro);
                LDSM4(al[mt], stA_lo + ro);
            }
            uint32_t bh[4][4], bl[4][4];
            #pragma unroll
            for (int g = 0; g < 4; g++) {
                const uint32_t ro = (uint32_t)((warp_n * 64 + g * 16 + lrow) * PITCH) * 2 + coff;
                LDSM4(bh[g], stB_hi + ro);
                LDSM4(bl[g], stB_lo + ro);
            }
            #pragma unroll
            for (int mt = 0; mt < 2; mt++)
                #pragma unroll
                for (int g = 0; g < 4; g++)
                    #pragma unroll
                    for (int s2 = 0; s2 < 2; s2++) {
                        const int nt = g * 2 + s2;
                        MMA16816(acc[mt][nt], ah[mt], bh[g][s2], bh[g][s2 + 2]);
                        MMA16816(acc[mt][nt], ah[mt], bl[g][s2], bl[g][s2 + 2]);
                        MMA16816(acc[mt][nt], al[mt], bh[g][s2], bh[g][s2 + 2]);
                    }
        }
        __syncthreads();
    }

    const int gid = lane >> 2;
    const int tig = lane & 3;
    #pragma unroll
    for (int mt = 0; mt < 2; mt++) {
        const int r0 = bm + warp_m * 32 + mt * 16 + gid;
        #pragma unroll
        for (int nt = 0; nt < 8; nt++) {
            const int c0 = bn + warp_n * 64 + nt * 8 + tig * 2;
            float b0 = bias ? bias[c0] : 0.f;
            float b1 = bias ? bias[c0 + 1] : 0.f;
            *(float2*)&C[(size_t)r0 * N + c0] =
                make_float2(acc[mt][nt][0] + b0, acc[mt][nt][1] + b1);
            *(float2*)&C[(size_t)(r0 + 8) * N + c0] =
                make_float2(acc[mt][nt][2] + b0, acc[mt][nt][3] + b1);
        }
    }
}

// ---------------------------------------------------------------------------
__global__ void transpose_proj(const float* __restrict__ P, float* __restrict__ PT)
{
    int idx = blockIdx.x * blockDim.x + threadIdx.x;
    int dd = idx >> 9;
    int j = idx & 511;
    PT[(size_t)j * DD + dd] = P[idx];
}

// ---------------------------------------------------------------------------
// RoPE + split: rotate q (pre-scaled by 0.125), k; split q,k,v to bf16 hi/lo.
// One thread per (m, h, j<32).
// ---------------------------------------------------------------------------
__device__ __forceinline__ void split_st(bf16* hi, bf16* lo, size_t o, float v) {
    bf16 h = __float2bfloat16(v);
    hi[o] = h;
    lo[o] = __float2bfloat16(v - __bfloat162float(h));
}

__global__ void rope_split(const float* __restrict__ qkv, const float* __restrict__ phases,
                           bf16* __restrict__ qh, bf16* __restrict__ ql,
                           bf16* __restrict__ kh, bf16* __restrict__ kl,
                           bf16* __restrict__ vh, bf16* __restrict__ vl)
{
    int idx = blockIdx.x * blockDim.x + threadIdx.x;   // MM*PH
    int m = idx >> 9;
    int r = idx & 511;
    int h = r >> 5;
    int j = r & 31;
    float ph = phases[idx];
    float s, c;
    __sincosf(ph, &s, &c);
    size_t ib = (size_t)m * E3 + h * HD + j;
    size_t ob = (size_t)m * DD + h * HD + j;
    float q1 = qkv[ib], q2 = qkv[ib + 32];
    split_st(qh, ql, ob,      (q1 * c - q2 * s) * 0.125f);
    split_st(qh, ql, ob + 32, (q1 * s + q2 * c) * 0.125f);
    float k1 = qkv[ib + DD], k2 = qkv[ib + DD + 32];
    split_st(kh, kl, ob,      k1 * c - k2 * s);
    split_st(kh, kl, ob + 32, k1 * s + k2 * c);
    split_st(vh, vl, ob,      qkv[ib + 2 * DD]);
    split_st(vh, vl, ob + 32, qkv[ib + 2 * DD + 32]);
}

// ---------------------------------------------------------------------------
// HMMA flash attention. grid=(L/64, H, B), 128 threads (4 warps, m16 each).
// Br=Bc=64, HD=64. 3-term bf16 split on QK^T and PV. Online softmax fp32.
// Writes O directly as bf16 hi/lo for the out-projection GEMM.
// ---------------------------------------------------------------------------
#define FPITCH 72
#define FROWB 144
#define FQH 0
#define FQL 9216
#define FKV 18432
#define FSTG 36864
#define F_KH 0
#define F_KL 9216
#define F_VH 18432
#define F_VL 27648
#define FLASH_SMEM (FKV + 2 * FSTG)   // 92160 B

__global__ __launch_bounds__(128) void flash_mma(
    const bf16* __restrict__ qh_g, const bf16* __restrict__ ql_g,
    const bf16* __restrict__ kh_g, const bf16* __restrict__ kl_g,
    const bf16* __restrict__ vh_g, const bf16* __restrict__ vl_g,
    bf16* __restrict__ oh_g, bf16* __restrict__ ol_g)
{
    extern __shared__ char smem[];
    const uint32_t sb = smem_u32(smem);
    const int tid = threadIdx.x;
    const int lane = tid & 31;
    const int warp = tid >> 5;
    const int b = blockIdx.z, h = blockIdx.y, qt = blockIdx.x;

    const size_t qrow0 = (size_t)b * LL + qt * 64;
    const size_t krow0 = (size_t)b * LL;
    const int hcol = h * HD;

    // ---- loaders: thread t covers row t>>1, 4 chunks of 16B ----
    const int lr = tid >> 1;
    const int lc4 = (tid & 1) * 4;
    const uint32_t dsto = (uint32_t)(lr * FROWB + lc4 * 16);
    const size_t srco = (size_t)lr * DD + hcol + lc4 * 8;

    auto cpa_tile = [&](uint32_t dst, const bf16* src) {
        CPA16(dst,      src);
        CPA16(dst + 16, src + 8);
        CPA16(dst + 32, src + 16);
        CPA16(dst + 48, src + 24);
    };
    auto issue_kv = [&](int kt, int s) {
        const uint32_t st = sb + FKV + s * FSTG + dsto;
        const size_t go = (size_t)kt * 64 * DD + srco;
        cpa_tile(st + F_KH, kh_g + krow0 * DD + go);
        cpa_tile(st + F_KL, kl_g + krow0 * DD + go);
        cpa_tile(st + F_VH, vh_g + krow0 * DD + go);
        cpa_tile(st + F_VL, vl_g + krow0 * DD + go);
    };

    // prologue: Q + stage 0
    cpa_tile(sb + FQH + dsto, qh_g + qrow0 * DD + srco);
    cpa_tile(sb + FQL + dsto, ql_g + qrow0 * DD + srco);
    issue_kv(0, 0);
    CPA_COMMIT();

    const int lrow = lane & 15;
    const int lsub = lane >> 4;
    const int gid = lane >> 2;
    const int tig = lane & 3;

    uint32_t qfh[4][4], qfl[4][4];
    float o[8][4];
    #pragma unroll
    for (int nt = 0; nt < 8; nt++)
        #pragma unroll
        for (int e = 0; e < 4; e++) o[nt][e] = 0.f;
    float m_a = -1e30f, m_b = -1e30f, l_a = 0.f, l_b = 0.f;

    for (int kt = 0; kt < LL / 64; kt++) {
        const int cur = kt & 1;
        if (kt + 1 < LL / 64) {
            issue_kv(kt + 1, cur ^ 1);
            CPA_COMMIT();
            CPA_WAIT1();
        } else {
            CPA_WAIT0();
        }
        __syncthreads();

        if (kt == 0) {
            #pragma unroll
            for (int ks = 0; ks < 4; ks++) {
                const uint32_t ro = (uint32_t)((warp * 16 + lrow) * FROWB + (ks * 16 + lsub * 8) * 2);
                LDSM4(qfh[ks], sb + FQH + ro);
                LDSM4(qfl[ks], sb + FQL + ro);
            }
        }

        const uint32_t kb = sb + FKV + cur * FSTG;

        // ---- S = Qh Kh^T + Qh Kl^T + Ql Kh^T ----
        float s[8][4];
        #pragma unroll
        for (int nt = 0; nt < 8; nt++)
            #pragma unroll
            for (int e = 0; e < 4; e++) s[nt][e] = 0.f;

        #pragma unroll
        for (int ks = 0; ks < 4; ks++)
            #pragma unroll
            for (int kg = 0; kg < 4; kg++) {
                const uint32_t ro = (uint32_t)((kg * 16 + lrow) * FROWB + (ks * 16 + lsub * 8) * 2);
                uint32_t k4h[4], k4l[4];
                LDSM4(k4h, kb + F_KH + ro);
                LDSM4(k4l, kb + F_KL + ro);
                MMA16816(s[2 * kg],     qfh[ks], k4h[0], k4h[2]);
                MMA16816(s[2 * kg + 1], qfh[ks], k4h[1], k4h[3]);
                MMA16816(s[2 * kg],     qfh[ks], k4l[0], k4l[2]);
                MMA16816(s[2 * kg + 1], qfh[ks], k4l[1], k4l[3]);
                MMA16816(s[2 * kg],     qfl[ks], k4h[0], k4h[2]);
                MMA16816(s[2 * kg + 1], qfl[ks], k4h[1], k4h[3]);
            }

        // ---- online softmax (rows: a=gid, b=gid+8) ----
        float mx_a = -1e30f, mx_b = -1e30f;
        #pragma unroll
        for (int nt = 0; nt < 8; nt++) {
            mx_a = fmaxf(mx_a, fmaxf(s[nt][0], s[nt][1]));
            mx_b = fmaxf(mx_b, fmaxf(s[nt][2], s[nt][3]));
        }
        #pragma unroll
        for (int off = 1; off <= 2; off <<= 1) {
            mx_a = fmaxf(mx_a, __shfl_xor_sync(0xffffffffu, mx_a, off));
            mx_b = fmaxf(mx_b, __shfl_xor_sync(0xffffffffu, mx_b, off));
        }
        const float mn_a = fmaxf(m_a, mx_a);
        const float mn_b = fmaxf(m_b, mx_b);
        const float sf_a = __expf(m_a - mn_a);
        const float sf_b = __expf(m_b - mn_b);
        m_a = mn_a; m_b = mn_b;

        float rs_a = 0.f, rs_b = 0.f;
        #pragma unroll
        for (int nt = 0; nt < 8; nt++) {
            s[nt][0] = __expf(s[nt][0] - mn_a);
            s[nt][1] = __expf(s[nt][1] - mn_a);
            s[nt][2] = __expf(s[nt][2] - mn_b);
            s[nt][3] = __expf(s[nt][3] - mn_b);
            rs_a += s[nt][0] + s[nt][1];
            rs_b += s[nt][2] + s[nt][3];
        }
        #pragma unroll
        for (int off = 1; off <= 2; off <<= 1) {
            rs_a += __shfl_xor_sync(0xffffffffu, rs_a, off);
            rs_b += __shfl_xor_sync(0xffffffffu, rs_b, off);
        }
        l_a = l_a * sf_a + rs_a;
        l_b = l_b * sf_b + rs_b;
        #pragma unroll
        for (int nt = 0; nt < 8; nt++) {
            o[nt][0] *= sf_a; o[nt][1] *= sf_a;
            o[nt][2] *= sf_b; o[nt][3] *= sf_b;
        }

        // ---- pack P into A fragments (hi/lo split) ----
        uint32_t ph[4][4], pl[4][4];
        #pragma unroll
        for (int kg = 0; kg < 4; kg++) {
            split_pack2(s[2 * kg][0],     s[2 * kg][1],     ph[kg][0], pl[kg][0]);
            split_pack2(s[2 * kg][2],     s[2 * kg][3],     ph[kg][1], pl[kg][1]);
            split_pack2(s[2 * kg + 1][0], s[2 * kg + 1][1], ph[kg][2], pl[kg][2]);
            split_pack2(s[2 * kg + 1][2], s[2 * kg + 1][3], ph[kg][3], pl[kg][3]);
        }

        // ---- O += Ph Vh + Ph Vl + Pl Vh  (V^T frags via ldmatrix.trans) ----
        #pragma unroll
        for (int kg = 0; kg < 4; kg++)
            #pragma unroll
            for (int dg = 0; dg < 4; dg++) {
                const uint32_t ro = (uint32_t)((kg * 16 + lrow) * FROWB + (dg * 16 + lsub * 8) * 2);
                uint32_t v4h[4], v4l[4];
                LDSM4T(v4h, kb + F_VH + ro);
                LDSM4T(v4l, kb + F_VL + ro);
                MMA16816(o[2 * dg],     ph[kg], v4h[0], v4h[1]);
                MMA16816(o[2 * dg + 1], ph[kg], v4h[2], v4h[3]);
                MMA16816(o[2 * dg],     ph[kg], v4l[0], v4l[1]);
                MMA16816(o[2 * dg + 1], ph[kg], v4l[2], v4l[3]);
                MMA16816(o[2 * dg],     pl[kg], v4h[0], v4h[1]);
                MMA16816(o[2 * dg + 1], pl[kg], v4h[2], v4h[3]);
            }
        __syncthreads();
    }

    // ---- epilogue: normalize, split to bf16 hi/lo, store ----
    const float inv_a = 1.0f / l_a;
    const float inv_b = 1.0f / l_b;
    const size_t row_a = qrow0 + warp * 16 + gid;
    const size_t row_b = row_a + 8;
    #pragma unroll
    for (int nt = 0; nt < 8; nt++) {
        const int col = hcol + nt * 8 + tig * 2;
        uint32_t hi, lo;
        split_pack2(o[nt][0] * inv_a, o[nt][1] * inv_a, hi, lo);
        *(uint32_t*)(oh_g + row_a * DD + col) = hi;
        *(uint32_t*)(ol_g + row_a * DD + col) = lo;
        split_pack2(o[nt][2] * inv_b, o[nt][3] * inv_b, hi, lo);
        *(uint32_t*)(oh_g + row_b * DD + col) = hi;
        *(uint32_t*)(ol_g + row_b * DD + col) = lo;
    }
}

// ---------------------------------------------------------------------------
extern "C" void kernel_launch(void* const* d_in, const int* in_sizes, int n_in,
                              void* d_out, int out_size)
{
    const float* x     = (const float*)d_in[0];
    const float* p     = (const float*)d_in[1];
    const float* W_qkv = (const float*)d_in[2];
    const float* b_qkv = (const float*)d_in[3];
    const float* W_out = (const float*)d_in[4];
    const float* b_out = (const float*)d_in[5];
    const float* proj  = (const float*)d_in[6];
    float* out = (float*)d_out;

    float *qkv, *phases, *projT;
    cudaGetSymbolAddress((void**)&qkv,    g_qkv);
    cudaGetSymbolAddress((void**)&phases, g_phases);
    cudaGetSymbolAddress((void**)&projT,  g_projT);
    bf16 *xh, *xl, *wqh, *wql, *ph2, *pl2, *pth, *ptl, *oh, *ol, *woh, *wol;
    bf16 *qh, *ql, *kh, *kl, *vh, *vl;
    cudaGetSymbolAddress((void**)&xh,  g_xh);  cudaGetSymbolAddress((void**)&xl,  g_xl);
    cudaGetSymbolAddress((void**)&wqh, g_wqh); cudaGetSymbolAddress((void**)&wql, g_wql);
    cudaGetSymbolAddress((void**)&ph2, g_ph2); cudaGetSymbolAddress((void**)&pl2, g_pl2);
    cudaGetSymbolAddress((void**)&pth, g_pth); cudaGetSymbolAddress((void**)&ptl, g_ptl);
    cudaGetSymbolAddress((void**)&oh,  g_oh);  cudaGetSymbolAddress((void**)&ol,  g_ol);
    cudaGetSymbolAddress((void**)&woh, g_woh); cudaGetSymbolAddress((void**)&wol, g_wol);
    cudaGetSymbolAddress((void**)&qh, g_qh); cudaGetSymbolAddress((void**)&ql, g_ql);
    cudaGetSymbolAddress((void**)&kh, g_kh); cudaGetSymbolAddress((void**)&kl, g_kl);
    cudaGetSymbolAddress((void**)&vh, g_vh); cudaGetSymbolAddress((void**)&vl, g_vl);

    cudaFuncSetAttribute(gemm_mma, cudaFuncAttributeMaxDynamicSharedMemorySize, GEMM_SMEM);
    cudaFuncSetAttribute(flash_mma, cudaFuncAttributeMaxDynamicSharedMemorySize, FLASH_SMEM);

    transpose_proj<<<(DD * PH) / 256, 256>>>(proj, projT);
    split_bf16<<<(MM * DD) / 256, 256>>>(x, xh, xl, MM * DD);
    split_bf16<<<(E3 * DD) / 256, 256>>>(W_qkv, wqh, wql, E3 * DD);
    split_bf16<<<(MM * DD) / 256, 256>>>(p, ph2, pl2, MM * DD);
    split_bf16<<<(PH * DD) / 256, 256>>>(projT, pth, ptl, PH * DD);

    // QKV GEMM + phases GEMM (fp32 outputs)
    gemm_mma<<<dim3(E3 / 128, MM / 128), 256, GEMM_SMEM>>>(xh, xl, wqh, wql, b_qkv, qkv, E3);
    gemm_mma<<<dim3(PH / 128, MM / 128), 256, GEMM_SMEM>>>(ph2, pl2, pth, ptl, nullptr, phases, PH);

    // RoPE + split q,k,v to bf16 hi/lo
    rope_split<<<(MM * PH) / 256, 256>>>(qkv, phases, qh, ql, kh, kl, vh, vl);

    // flash attention (HMMA) -> bf16 hi/lo O
    flash_mma<<<dim3(LL / 64, HH, BB), 128, FLASH_SMEM>>>(qh, ql, kh, kl, vh, vl, oh, ol);

    // out GEMM
    split_bf16<<<(DD * DD) / 256, 256>>>(W_out, woh, wol, DD * DD);
    gemm_mma<<<dim3(DD / 128, MM / 128), 256, GEMM_SMEM>>>(oh, ol, woh, wol, b_out, out, DD);
}

// round 8
// speedup vs baseline: 2.4039x; 1.1562x over previous
#include <cuda_runtime.h>
#include <cuda_bf16.h>
#include <cstdint>

#define BB 2
#define LL 2048
#define DD 1024
#define HH 16
#define HD 64
#define MM (BB*LL)          // 4096
#define E3 (3*DD)           // 3072
#define PH (DD/2)           // 512
#define GK DD               // GEMM K=1024

typedef unsigned long long ull;
typedef __nv_bfloat16 bf16;

// ---------------- scratch ----------------
__device__ float g_qkv[MM * E3];
__device__ float g_phases[MM * PH];
__device__ float g_projT[PH * DD];
__device__ bf16 g_xh[MM*DD],  g_xl[MM*DD];
__device__ bf16 g_wqh[E3*DD], g_wql[E3*DD];
__device__ bf16 g_ph2[MM*DD], g_pl2[MM*DD];
__device__ bf16 g_pth[PH*DD], g_ptl[PH*DD];
__device__ bf16 g_oh[MM*DD],  g_ol[MM*DD];
__device__ bf16 g_woh[DD*DD], g_wol[DD*DD];
__device__ bf16 g_qh[MM*DD], g_ql[MM*DD];
__device__ bf16 g_kh[MM*DD], g_kl[MM*DD];
__device__ bf16 g_vh[MM*DD], g_vl[MM*DD];

// ---------------- PTX helpers ----------------
__device__ __forceinline__ uint32_t smem_u32(const void* p) {
    uint32_t a;
    asm("{ .reg .u64 t; cvta.to.shared.u64 t, %1; cvt.u32.u64 %0, t; }" : "=r"(a) : "l"(p));
    return a;
}
#define LDSM4(R, addr) \
    asm volatile("ldmatrix.sync.aligned.m8n8.x4.shared.b16 {%0,%1,%2,%3}, [%4];" \
        : "=r"((R)[0]), "=r"((R)[1]), "=r"((R)[2]), "=r"((R)[3]) : "r"(addr))
#define LDSM4T(R, addr) \
    asm volatile("ldmatrix.sync.aligned.m8n8.x4.trans.shared.b16 {%0,%1,%2,%3}, [%4];" \
        : "=r"((R)[0]), "=r"((R)[1]), "=r"((R)[2]), "=r"((R)[3]) : "r"(addr))
#define MMA16816(D, A, B0, B1) \
    asm volatile("mma.sync.aligned.m16n8k16.row.col.f32.bf16.bf16.f32 " \
        "{%0,%1,%2,%3}, {%4,%5,%6,%7}, {%8,%9}, {%0,%1,%2,%3};" \
        : "+f"((D)[0]), "+f"((D)[1]), "+f"((D)[2]), "+f"((D)[3]) \
        : "r"((A)[0]), "r"((A)[1]), "r"((A)[2]), "r"((A)[3]), "r"(B0), "r"(B1))
#define CPA16(dst, src) \
    asm volatile("cp.async.cg.shared.global [%0], [%1], 16;" :: "r"(dst), "l"(src))
#define CPA_COMMIT() asm volatile("cp.async.commit_group;" ::: "memory")
#define CPA_WAIT1()  asm volatile("cp.async.wait_group 1;" ::: "memory")
#define CPA_WAIT0()  asm volatile("cp.async.wait_group 0;" ::: "memory")

union BF2U { __nv_bfloat162 b; uint32_t u; };
__device__ __forceinline__ void split_pack2(float e0, float e1, uint32_t& hi, uint32_t& lo) {
    bf16 h0 = __float2bfloat16(e0), h1 = __float2bfloat16(e1);
    float r0 = e0 - __bfloat162float(h0), r1 = e1 - __bfloat162float(h1);
    BF2U a, b2;
    a.b  = __halves2bfloat162(h0, h1);
    b2.b = __halves2bfloat162(__float2bfloat16(r0), __float2bfloat16(r1));
    hi = a.u; lo = b2.u;
}

// ---------------------------------------------------------------------------
// fp32 -> (hi, lo) bf16 split, 4 elems/thread
// ---------------------------------------------------------------------------
__global__ void split_bf16(const float* __restrict__ src,
                           bf16* __restrict__ hi, bf16* __restrict__ lo, int n)
{
    int i = (blockIdx.x * blockDim.x + threadIdx.x) * 4;
    if (i < n) {
        float4 v = *(const float4*)(src + i);
        uint32_t h0, l0, h1, l1;
        split_pack2(v.x, v.y, h0, l0);
        split_pack2(v.z, v.w, h1, l1);
        *(uint2*)(hi + i) = make_uint2(h0, h1);
        *(uint2*)(lo + i) = make_uint2(l0, l1);
    }
}

// ---------------------------------------------------------------------------
// HMMA NT GEMM: C = A @ B^T (+bias). Term-major MMA ordering (acc distance 16).
// ---------------------------------------------------------------------------
#define PITCH 40
#define BUF_B (128 * PITCH * 2)
#define STAGE_B (4 * BUF_B)
#define GEMM_SMEM (2 * STAGE_B)
#define NKC (GK / 32)

__global__ __launch_bounds__(256) void gemm_mma(
    const bf16* __restrict__ Ahi, const bf16* __restrict__ Alo,
    const bf16* __restrict__ Bhi, const bf16* __restrict__ Blo,
    const float* __restrict__ bias, float* __restrict__ C, int N)
{
    extern __shared__ char smem[];
    const uint32_t sb = smem_u32(smem);
    const int tid = threadIdx.x;
    const int lane = tid & 31;
    const int wid = tid >> 5;
    const int warp_m = wid >> 1;
    const int warp_n = wid & 1;
    const int bm = blockIdx.y * 128;
    const int bn = blockIdx.x * 128;

    const int lr = tid >> 1;
    const int lh = tid & 1;
    const bf16* gAh = Ahi + (size_t)(bm + lr) * GK + lh * 16;
    const bf16* gAl = Alo + (size_t)(bm + lr) * GK + lh * 16;
    const bf16* gBh = Bhi + (size_t)(bn + lr) * GK + lh * 16;
    const bf16* gBl = Blo + (size_t)(bn + lr) * GK + lh * 16;
    const uint32_t srow = sb + (uint32_t)(lr * PITCH + lh * 16) * 2;

    auto issue_stage = [&](int kc, int s) {
        const uint32_t st = srow + s * STAGE_B;
        const size_t go = (size_t)kc * 32;
        CPA16(st + 0 * BUF_B,      gAh + go);
        CPA16(st + 0 * BUF_B + 16, gAh + go + 8);
        CPA16(st + 1 * BUF_B,      gAl + go);
        CPA16(st + 1 * BUF_B + 16, gAl + go + 8);
        CPA16(st + 2 * BUF_B,      gBh + go);
        CPA16(st + 2 * BUF_B + 16, gBh + go + 8);
        CPA16(st + 3 * BUF_B,      gBl + go);
        CPA16(st + 3 * BUF_B + 16, gBl + go + 8);
    };

    float acc[2][8][4];
    #pragma unroll
    for (int mt = 0; mt < 2; mt++)
        #pragma unroll
        for (int nt = 0; nt < 8; nt++)
            #pragma unroll
            for (int e = 0; e < 4; e++) acc[mt][nt][e] = 0.f;

    const int lrow = lane & 15;
    const int lsub = lane >> 4;

    issue_stage(0, 0);
    CPA_COMMIT();

    for (int kc = 0; kc < NKC; kc++) {
        const int cur = kc & 1;
        if (kc + 1 < NKC) {
            issue_stage(kc + 1, cur ^ 1);
            CPA_COMMIT();
            CPA_WAIT1();
        } else {
            CPA_WAIT0();
        }
        __syncthreads();

        const uint32_t stA_hi = sb + cur * STAGE_B;
        const uint32_t stA_lo = stA_hi + BUF_B;
        const uint32_t stB_hi = stA_hi + 2 * BUF_B;
        const uint32_t stB_lo = stA_hi + 3 * BUF_B;

        #pragma unroll
        for (int h = 0; h < 2; h++) {
            const uint32_t coff = (uint32_t)(h * 16 + lsub * 8) * 2;
            uint32_t ah[2][4], al[2][4];
            #pragma unroll
            for (int mt = 0; mt < 2; mt++) {
                const uint32_t ro = (uint32_t)((warp_m * 32 + mt * 16 + lrow) * PITCH) * 2 + coff;
                LDSM4(ah[mt], stA_hi + ro);
                LDSM4(al[mt], stA_lo + ro);
            }
            uint32_t bh[4][4], bl[4][4];
            #pragma unroll
            for (int g = 0; g < 4; g++) {
                const uint32_t ro = (uint32_t)((warp_n * 64 + g * 16 + lrow) * PITCH) * 2 + coff;
                LDSM4(bh[g], stB_hi + ro);
                LDSM4(bl[g], stB_lo + ro);
            }
            // term-major: same accumulator reused only every 16 MMAs
            #pragma unroll
            for (int mt = 0; mt < 2; mt++)
                #pragma unroll
                for (int g = 0; g < 4; g++)
                    #pragma unroll
                    for (int s2 = 0; s2 < 2; s2++)
                        MMA16816(acc[mt][g * 2 + s2], ah[mt], bh[g][s2], bh[g][s2 + 2]);
            #pragma unroll
            for (int mt = 0; mt < 2; mt++)
                #pragma unroll
                for (int g = 0; g < 4; g++)
                    #pragma unroll
                    for (int s2 = 0; s2 < 2; s2++)
                        MMA16816(acc[mt][g * 2 + s2], ah[mt], bl[g][s2], bl[g][s2 + 2]);
            #pragma unroll
            for (int mt = 0; mt < 2; mt++)
                #pragma unroll
                for (int g = 0; g < 4; g++)
                    #pragma unroll
                    for (int s2 = 0; s2 < 2; s2++)
                        MMA16816(acc[mt][g * 2 + s2], al[mt], bh[g][s2], bh[g][s2 + 2]);
        }
        __syncthreads();
    }

    const int gid = lane >> 2;
    const int tig = lane & 3;
    #pragma unroll
    for (int mt = 0; mt < 2; mt++) {
        const int r0 = bm + warp_m * 32 + mt * 16 + gid;
        #pragma unroll
        for (int nt = 0; nt < 8; nt++) {
            const int c0 = bn + warp_n * 64 + nt * 8 + tig * 2;
            float b0 = bias ? bias[c0] : 0.f;
            float b1 = bias ? bias[c0 + 1] : 0.f;
            *(float2*)&C[(size_t)r0 * N + c0] =
                make_float2(acc[mt][nt][0] + b0, acc[mt][nt][1] + b1);
            *(float2*)&C[(size_t)(r0 + 8) * N + c0] =
                make_float2(acc[mt][nt][2] + b0, acc[mt][nt][3] + b1);
        }
    }
}

// ---------------------------------------------------------------------------
__global__ void transpose_proj(const float* __restrict__ P, float* __restrict__ PT)
{
    int idx = blockIdx.x * blockDim.x + threadIdx.x;
    int dd = idx >> 9;
    int j = idx & 511;
    PT[(size_t)j * DD + dd] = P[idx];
}

// ---------------------------------------------------------------------------
__device__ __forceinline__ void split_st(bf16* hi, bf16* lo, size_t o, float v) {
    bf16 h = __float2bfloat16(v);
    hi[o] = h;
    lo[o] = __float2bfloat16(v - __bfloat162float(h));
}

__global__ void rope_split(const float* __restrict__ qkv, const float* __restrict__ phases,
                           bf16* __restrict__ qh, bf16* __restrict__ ql,
                           bf16* __restrict__ kh, bf16* __restrict__ kl,
                           bf16* __restrict__ vh, bf16* __restrict__ vl)
{
    int idx = blockIdx.x * blockDim.x + threadIdx.x;   // MM*PH
    int m = idx >> 9;
    int r = idx & 511;
    int h = r >> 5;
    int j = r & 31;
    float ph = phases[idx];
    float s, c;
    __sincosf(ph, &s, &c);
    size_t ib = (size_t)m * E3 + h * HD + j;
    size_t ob = (size_t)m * DD + h * HD + j;
    float q1 = qkv[ib], q2 = qkv[ib + 32];
    split_st(qh, ql, ob,      (q1 * c - q2 * s) * 0.125f);
    split_st(qh, ql, ob + 32, (q1 * s + q2 * c) * 0.125f);
    float k1 = qkv[ib + DD], k2 = qkv[ib + DD + 32];
    split_st(kh, kl, ob,      k1 * c - k2 * s);
    split_st(kh, kl, ob + 32, k1 * s + k2 * c);
    split_st(vh, vl, ob,      qkv[ib + 2 * DD]);
    split_st(vh, vl, ob + 32, qkv[ib + 2 * DD + 32]);
}

// ---------------------------------------------------------------------------
// HMMA flash attention. grid=(L/128, H, B), 256 threads (8 warps, 16 q-rows each).
// 128 queries share K/V stages. Term-major MMA ordering.
// ---------------------------------------------------------------------------
#define FROWB 144
#define FQH 0
#define FQL 18432
#define FKV 36864
#define FSTG 36864
#define F_KH 0
#define F_KL 9216
#define F_VH 18432
#define F_VL 27648
#define FLASH_SMEM (FKV + 2 * FSTG)   // 110592 B

__global__ __launch_bounds__(256) void flash_mma(
    const bf16* __restrict__ qh_g, const bf16* __restrict__ ql_g,
    const bf16* __restrict__ kh_g, const bf16* __restrict__ kl_g,
    const bf16* __restrict__ vh_g, const bf16* __restrict__ vl_g,
    bf16* __restrict__ oh_g, bf16* __restrict__ ol_g)
{
    extern __shared__ char smem[];
    const uint32_t sb = smem_u32(smem);
    const int tid = threadIdx.x;
    const int lane = tid & 31;
    const int warp = tid >> 5;
    const int b = blockIdx.z, h = blockIdx.y, qt = blockIdx.x;

    const size_t qrow0 = (size_t)b * LL + qt * 128;
    const size_t krow0 = (size_t)b * LL;
    const int hcol = h * HD;

    // Q loader: row = tid>>1 (0..127), 4 chunks of 16B
    const int qlr = tid >> 1;
    const int qlc = (tid & 1) * 4;
    const uint32_t qdst = (uint32_t)(qlr * FROWB + qlc * 16);
    const size_t qsrc = (size_t)qlr * DD + hcol + qlc * 8;
    // KV loader: row = tid>>2 (0..63), 2 chunks of 16B
    const int klr = tid >> 2;
    const int klc = (tid & 3) * 2;
    const uint32_t kdst = (uint32_t)(klr * FROWB + klc * 16);
    const size_t ksrc = (size_t)klr * DD + hcol + klc * 8;

    auto issue_kv = [&](int kt, int s) {
        const uint32_t st = sb + FKV + s * FSTG + kdst;
        const size_t go = (size_t)kt * 64 * DD + krow0 * DD + ksrc;
        CPA16(st + F_KH,      kh_g + go);
        CPA16(st + F_KH + 16, kh_g + go + 8);
        CPA16(st + F_KL,      kl_g + go);
        CPA16(st + F_KL + 16, kl_g + go + 8);
        CPA16(st + F_VH,      vh_g + go);
        CPA16(st + F_VH + 16, vh_g + go + 8);
        CPA16(st + F_VL,      vl_g + go);
        CPA16(st + F_VL + 16, vl_g + go + 8);
    };

    // prologue: Q + stage 0
    {
        const bf16* s0 = qh_g + qrow0 * DD + qsrc;
        const bf16* s1 = ql_g + qrow0 * DD + qsrc;
        CPA16(sb + FQH + qdst,      s0);     CPA16(sb + FQH + qdst + 16, s0 + 8);
        CPA16(sb + FQH + qdst + 32, s0 + 16); CPA16(sb + FQH + qdst + 48, s0 + 24);
        CPA16(sb + FQL + qdst,      s1);     CPA16(sb + FQL + qdst + 16, s1 + 8);
        CPA16(sb + FQL + qdst + 32, s1 + 16); CPA16(sb + FQL + qdst + 48, s1 + 24);
    }
    issue_kv(0, 0);
    CPA_COMMIT();

    const int lrow = lane & 15;
    const int lsub = lane >> 4;
    const int gid = lane >> 2;
    const int tig = lane & 3;

    uint32_t qfh[4][4], qfl[4][4];
    float o[8][4];
    #pragma unroll
    for (int nt = 0; nt < 8; nt++)
        #pragma unroll
        for (int e = 0; e < 4; e++) o[nt][e] = 0.f;
    float m_a = -1e30f, m_b = -1e30f, l_a = 0.f, l_b = 0.f;

    for (int kt = 0; kt < LL / 64; kt++) {
        const int cur = kt & 1;
        if (kt + 1 < LL / 64) {
            issue_kv(kt + 1, cur ^ 1);
            CPA_COMMIT();
            CPA_WAIT1();
        } else {
            CPA_WAIT0();
        }
        __syncthreads();

        if (kt == 0) {
            #pragma unroll
            for (int ks = 0; ks < 4; ks++) {
                const uint32_t ro = (uint32_t)((warp * 16 + lrow) * FROWB + (ks * 16 + lsub * 8) * 2);
                LDSM4(qfh[ks], sb + FQH + ro);
                LDSM4(qfl[ks], sb + FQL + ro);
            }
        }

        const uint32_t kb = sb + FKV + cur * FSTG;

        // ---- S = Qh Kh + Qh Kl + Ql Kh (term-major, acc distance 8) ----
        float s[8][4];
        #pragma unroll
        for (int nt = 0; nt < 8; nt++)
            #pragma unroll
            for (int e = 0; e < 4; e++) s[nt][e] = 0.f;

        #pragma unroll
        for (int ks = 0; ks < 4; ks++) {
            uint32_t kfh[4][4], kfl[4][4];
            #pragma unroll
            for (int kg = 0; kg < 4; kg++) {
                const uint32_t ro = (uint32_t)((kg * 16 + lrow) * FROWB + (ks * 16 + lsub * 8) * 2);
                LDSM4(kfh[kg], kb + F_KH + ro);
                LDSM4(kfl[kg], kb + F_KL + ro);
            }
            #pragma unroll
            for (int kg = 0; kg < 4; kg++) {
                MMA16816(s[2 * kg],     qfh[ks], kfh[kg][0], kfh[kg][2]);
                MMA16816(s[2 * kg + 1], qfh[ks], kfh[kg][1], kfh[kg][3]);
            }
            #pragma unroll
            for (int kg = 0; kg < 4; kg++) {
                MMA16816(s[2 * kg],     qfh[ks], kfl[kg][0], kfl[kg][2]);
                MMA16816(s[2 * kg + 1], qfh[ks], kfl[kg][1], kfl[kg][3]);
            }
            #pragma unroll
            for (int kg = 0; kg < 4; kg++) {
                MMA16816(s[2 * kg],     qfl[ks], kfh[kg][0], kfh[kg][2]);
                MMA16816(s[2 * kg + 1], qfl[ks], kfh[kg][1], kfh[kg][3]);
            }
        }

        // ---- online softmax ----
        float mx_a = -1e30f, mx_b = -1e30f;
        #pragma unroll
        for (int nt = 0; nt < 8; nt++) {
            mx_a = fmaxf(mx_a, fmaxf(s[nt][0], s[nt][1]));
            mx_b = fmaxf(mx_b, fmaxf(s[nt][2], s[nt][3]));
        }
        #pragma unroll
        for (int off = 1; off <= 2; off <<= 1) {
            mx_a = fmaxf(mx_a, __shfl_xor_sync(0xffffffffu, mx_a, off));
            mx_b = fmaxf(mx_b, __shfl_xor_sync(0xffffffffu, mx_b, off));
        }
        const float mn_a = fmaxf(m_a, mx_a);
        const float mn_b = fmaxf(m_b, mx_b);
        const float sf_a = __expf(m_a - mn_a);
        const float sf_b = __expf(m_b - mn_b);
        m_a = mn_a; m_b = mn_b;

        float rs_a = 0.f, rs_b = 0.f;
        #pragma unroll
        for (int nt = 0; nt < 8; nt++) {
            s[nt][0] = __expf(s[nt][0] - mn_a);
            s[nt][1] = __expf(s[nt][1] - mn_a);
            s[nt][2] = __expf(s[nt][2] - mn_b);
            s[nt][3] = __expf(s[nt][3] - mn_b);
            rs_a += s[nt][0] + s[nt][1];
            rs_b += s[nt][2] + s[nt][3];
        }
        #pragma unroll
        for (int off = 1; off <= 2; off <<= 1) {
            rs_a += __shfl_xor_sync(0xffffffffu, rs_a, off);
            rs_b += __shfl_xor_sync(0xffffffffu, rs_b, off);
        }
        l_a = l_a * sf_a + rs_a;
        l_b = l_b * sf_b + rs_b;
        #pragma unroll
        for (int nt = 0; nt < 8; nt++) {
            o[nt][0] *= sf_a; o[nt][1] *= sf_a;
            o[nt][2] *= sf_b; o[nt][3] *= sf_b;
        }

        // ---- pack P fragments (hi/lo) ----
        uint32_t ph[4][4], pl[4][4];
        #pragma unroll
        for (int kg = 0; kg < 4; kg++) {
            split_pack2(s[2 * kg][0],     s[2 * kg][1],     ph[kg][0], pl[kg][0]);
            split_pack2(s[2 * kg][2],     s[2 * kg][3],     ph[kg][1], pl[kg][1]);
            split_pack2(s[2 * kg + 1][0], s[2 * kg + 1][1], ph[kg][2], pl[kg][2]);
            split_pack2(s[2 * kg + 1][2], s[2 * kg + 1][3], ph[kg][3], pl[kg][3]);
        }

        // ---- O += Ph Vh + Ph Vl + Pl Vh (term-major per kg) ----
        #pragma unroll
        for (int kg = 0; kg < 4; kg++) {
            uint32_t vfh[4][4], vfl[4][4];
            #pragma unroll
            for (int dg = 0; dg < 4; dg++) {
                const uint32_t ro = (uint32_t)((kg * 16 + lrow) * FROWB + (dg * 16 + lsub * 8) * 2);
                LDSM4T(vfh[dg], kb + F_VH + ro);
                LDSM4T(vfl[dg], kb + F_VL + ro);
            }
            #pragma unroll
            for (int dg = 0; dg < 4; dg++) {
                MMA16816(o[2 * dg],     ph[kg], vfh[dg][0], vfh[dg][1]);
                MMA16816(o[2 * dg + 1], ph[kg], vfh[dg][2], vfh[dg][3]);
            }
            #pragma unroll
            for (int dg = 0; dg < 4; dg++) {
                MMA16816(o[2 * dg],     ph[kg], vfl[dg][0], vfl[dg][1]);
                MMA16816(o[2 * dg + 1], ph[kg], vfl[dg][2], vfl[dg][3]);
            }
            #pragma unroll
            for (int dg = 0; dg < 4; dg++) {
                MMA16816(o[2 * dg],     pl[kg], vfh[dg][0], vfh[dg][1]);
                MMA16816(o[2 * dg + 1], pl[kg], vfh[dg][2], vfh[dg][3]);
            }
        }
        __syncthreads();
    }

    // ---- epilogue ----
    const float inv_a = 1.0f / l_a;
    const float inv_b = 1.0f / l_b;
    const size_t row_a = qrow0 + warp * 16 + gid;
    const size_t row_b = row_a + 8;
    #pragma unroll
    for (int nt = 0; nt < 8; nt++) {
        const int col = hcol + nt * 8 + tig * 2;
        uint32_t hi, lo;
        split_pack2(o[nt][0] * inv_a, o[nt][1] * inv_a, hi, lo);
        *(uint32_t*)(oh_g + row_a * DD + col) = hi;
        *(uint32_t*)(ol_g + row_a * DD + col) = lo;
        split_pack2(o[nt][2] * inv_b, o[nt][3] * inv_b, hi, lo);
        *(uint32_t*)(oh_g + row_b * DD + col) = hi;
        *(uint32_t*)(ol_g + row_b * DD + col) = lo;
    }
}

// ---------------------------------------------------------------------------
extern "C" void kernel_launch(void* const* d_in, const int* in_sizes, int n_in,
                              void* d_out, int out_size)
{
    const float* x     = (const float*)d_in[0];
    const float* p     = (const float*)d_in[1];
    const float* W_qkv = (const float*)d_in[2];
    const float* b_qkv = (const float*)d_in[3];
    const float* W_out = (const float*)d_in[4];
    const float* b_out = (const float*)d_in[5];
    const float* proj  = (const float*)d_in[6];
    float* out = (float*)d_out;

    float *qkv, *phases, *projT;
    cudaGetSymbolAddress((void**)&qkv,    g_qkv);
    cudaGetSymbolAddress((void**)&phases, g_phases);
    cudaGetSymbolAddress((void**)&projT,  g_projT);
    bf16 *xh, *xl, *wqh, *wql, *ph2, *pl2, *pth, *ptl, *oh, *ol, *woh, *wol;
    bf16 *qh, *ql, *kh, *kl, *vh, *vl;
    cudaGetSymbolAddress((void**)&xh,  g_xh);  cudaGetSymbolAddress((void**)&xl,  g_xl);
    cudaGetSymbolAddress((void**)&wqh, g_wqh); cudaGetSymbolAddress((void**)&wql, g_wql);
    cudaGetSymbolAddress((void**)&ph2, g_ph2); cudaGetSymbolAddress((void**)&pl2, g_pl2);
    cudaGetSymbolAddress((void**)&pth, g_pth); cudaGetSymbolAddress((void**)&ptl, g_ptl);
    cudaGetSymbolAddress((void**)&oh,  g_oh);  cudaGetSymbolAddress((void**)&ol,  g_ol);
    cudaGetSymbolAddress((void**)&woh, g_woh); cudaGetSymbolAddress((void**)&wol, g_wol);
    cudaGetSymbolAddress((void**)&qh, g_qh); cudaGetSymbolAddress((void**)&ql, g_ql);
    cudaGetSymbolAddress((void**)&kh, g_kh); cudaGetSymbolAddress((void**)&kl, g_kl);
    cudaGetSymbolAddress((void**)&vh, g_vh); cudaGetSymbolAddress((void**)&vl, g_vl);

    cudaFuncSetAttribute(gemm_mma, cudaFuncAttributeMaxDynamicSharedMemorySize, GEMM_SMEM);
    cudaFuncSetAttribute(flash_mma, cudaFuncAttributeMaxDynamicSharedMemorySize, FLASH_SMEM);

    transpose_proj<<<(DD * PH) / 256, 256>>>(proj, projT);
    split_bf16<<<(MM * DD) / 1024, 256>>>(x, xh, xl, MM * DD);
    split_bf16<<<(E3 * DD) / 1024, 256>>>(W_qkv, wqh, wql, E3 * DD);
    split_bf16<<<(MM * DD) / 1024, 256>>>(p, ph2, pl2, MM * DD);
    split_bf16<<<(PH * DD) / 1024, 256>>>(projT, pth, ptl, PH * DD);

    gemm_mma<<<dim3(E3 / 128, MM / 128), 256, GEMM_SMEM>>>(xh, xl, wqh, wql, b_qkv, qkv, E3);
    gemm_mma<<<dim3(PH / 128, MM / 128), 256, GEMM_SMEM>>>(ph2, pl2, pth, ptl, nullptr, phases, PH);

    rope_split<<<(MM * PH) / 256, 256>>>(qkv, phases, qh, ql, kh, kl, vh, vl);

    flash_mma<<<dim3(LL / 128, HH, BB), 256, FLASH_SMEM>>>(qh, ql, kh, kl, vh, vl, oh, ol);

    split_bf16<<<(DD * DD) / 1024, 256>>>(W_out, woh, wol, DD * DD);
    gemm_mma<<<dim3(DD / 128, MM / 128), 256, GEMM_SMEM>>>(oh, ol, woh, wol, b_out, out, DD);
}